// round 3
// baseline (speedup 1.0000x reference)
#include <cuda_runtime.h>
#include <math.h>
#include <stdint.h>

// ---------------------------------------------------------------------------
// TextGRUClassifier: 2-layer bidir GRU (B=256,T=512,E=128,H=160) + FC head
// R3: gates GEMMs on tf32 mma.sync tensor cores; scan rebalanced to 640 thr
//     (thread = one (h-unit, batch) pair), 28/40 Whh k-quads in smem.
// ---------------------------------------------------------------------------

#define Tt 512
#define Bb 256
#define Hh 160
#define G3 480
#define Mrows (Tt*Bb)     // 131072
#define SKQ 28            // k-quads of Whh kept in smem (of 40)

typedef unsigned long long u64;

// ---- scratch ----
static __device__ float g_gi0[(size_t)2 * Mrows * G3];
static __device__ float g_gi1[(size_t)2 * Mrows * G3];
static __device__ float g_y0[(size_t)Mrows * 320];
static __device__ float g_whhP[4 * 40 * G3 * 4];
static __device__ float g_hfin[2 * Bb * Hh];

// ---- helpers ----
__device__ __forceinline__ void unpack2(u64 v, float& x, float& y) {
    asm("mov.b64 {%0, %1}, %2;" : "=f"(x), "=f"(y) : "l"(v));
}
__device__ __forceinline__ void fma2(u64& d, u64 a, u64 b) {
    asm("fma.rn.f32x2 %0, %1, %2, %0;" : "+l"(d) : "l"(a), "l"(b));
}
__device__ __forceinline__ float sigm_f(float x) { return 1.f / (1.f + __expf(-x)); }

__device__ __forceinline__ uint32_t f2tf32(float x) {
    uint32_t r;
    asm("cvt.rna.tf32.f32 %0, %1;" : "=r"(r) : "f"(x));
    return r;
}
__device__ __forceinline__ void mma_tf32(float* d, const uint32_t* a, const uint32_t* b) {
    asm volatile(
        "mma.sync.aligned.m16n8k8.row.col.f32.tf32.tf32.f32 "
        "{%0,%1,%2,%3}, {%4,%5,%6,%7}, {%8,%9}, {%0,%1,%2,%3};"
        : "+f"(d[0]), "+f"(d[1]), "+f"(d[2]), "+f"(d[3])
        : "r"(a[0]), "r"(a[1]), "r"(a[2]), "r"(a[3]), "r"(b[0]), "r"(b[1]));
}

// ---------------------------------------------------------------------------
// K0: pack Whh[g][k] -> whhP[dl][kq][g][k%4]
// ---------------------------------------------------------------------------
__global__ void pack_whh_kernel(const float* __restrict__ w0f, const float* __restrict__ w0b,
                                const float* __restrict__ w1f, const float* __restrict__ w1b,
                                float* __restrict__ wp) {
    int dl = blockIdx.x;
    const float* w = (dl == 0) ? w0f : (dl == 1) ? w0b : (dl == 2) ? w1f : w1b;
    for (int i = threadIdx.x; i < G3 * Hh; i += blockDim.x) {
        int g = i / Hh, k = i % Hh;
        wp[(((size_t)dl * 40 + (k >> 2)) * G3 + g) * 4 + (k & 3)] = w[i];
    }
}

// ---------------------------------------------------------------------------
// K1/K3: gates GEMM on tf32 tensor cores.
//   out[dir][m][n] = W_dir[n][:] . A_row(m) + bias_dir[n]
//   Tile BM=128 BN=96 BK=32, 256 thr (8 warps = 4x2), 2x6 m16n8k8 frags/warp.
// ---------------------------------------------------------------------------
#define ALD 36   // padded row stride (floats) for As/Bs -> conflict-free frag loads

template <int KDIM, bool GATHER>
__global__ __launch_bounds__(256, 2)
void gates_mma_kernel(const float* __restrict__ A, const int* __restrict__ xids,
                      const float* __restrict__ Wf, const float* __restrict__ Wb,
                      const float* __restrict__ bf, const float* __restrict__ bb,
                      float* __restrict__ out) {
    const int m0 = blockIdx.x * 128;
    const int n0 = blockIdx.y * 96;
    const int dir = blockIdx.z;
    const float* W = dir ? Wb : Wf;
    const float* bias = dir ? bb : bf;
    float* outp = out + (size_t)dir * Mrows * G3;

    __shared__ float As[128 * ALD];   // [m][k], tf32-rounded
    __shared__ float Bs[96 * ALD];    // [n][k], tf32-rounded
    __shared__ int rid[128];

    const int tid = threadIdx.x;
    if (GATHER) {
        if (tid < 128) {
            int m = m0 + tid;
            rid[tid] = xids[(m & 255) * Tt + (m >> 8)];
        }
        __syncthreads();
    }

    const int lane = tid & 31, wid = tid >> 5;
    const int grp = lane >> 2, tq = lane & 3;
    const int m_off = (wid >> 1) * 32;   // warp M origin (0,32,64,96)
    const int n_off = (wid & 1) * 48;    // warp N origin (0,48)

    float acc[2][6][4];
#pragma unroll
    for (int i = 0; i < 2; i++)
#pragma unroll
        for (int j = 0; j < 6; j++)
#pragma unroll
            for (int c = 0; c < 4; c++) acc[i][j][c] = 0.f;

    // staging coordinates: idx = tid + u*256 ; row = idx>>3 ; kquad = tid&7
    const int rA = tid >> 3;      // 0..31
    const int cA = tid & 7;       // 0..7
    const float* arow[4];
#pragma unroll
    for (int u = 0; u < 4; u++) {
        int r = rA + u * 32;
        arow[u] = GATHER ? A + (size_t)rid[r] * KDIM : A + (size_t)(m0 + r) * KDIM;
    }
    const float* brow[3];
#pragma unroll
    for (int u = 0; u < 3; u++) brow[u] = W + (size_t)(n0 + rA + u * 32) * KDIM;

    const int KT = KDIM / 32;
    float4 aR[4], bR[3];

    // prologue: load tile 0
#pragma unroll
    for (int u = 0; u < 4; u++) aR[u] = *(const float4*)(arow[u] + cA * 4);
#pragma unroll
    for (int u = 0; u < 3; u++) bR[u] = *(const float4*)(brow[u] + cA * 4);

    for (int kt = 0; kt < KT; kt++) {
        __syncthreads();   // previous tile's consumers done
#pragma unroll
        for (int u = 0; u < 4; u++) {
            float4 v = aR[u];
            float4 w4 = make_float4(__uint_as_float(f2tf32(v.x)), __uint_as_float(f2tf32(v.y)),
                                    __uint_as_float(f2tf32(v.z)), __uint_as_float(f2tf32(v.w)));
            *(float4*)&As[(rA + u * 32) * ALD + cA * 4] = w4;
        }
#pragma unroll
        for (int u = 0; u < 3; u++) {
            float4 v = bR[u];
            float4 w4 = make_float4(__uint_as_float(f2tf32(v.x)), __uint_as_float(f2tf32(v.y)),
                                    __uint_as_float(f2tf32(v.z)), __uint_as_float(f2tf32(v.w)));
            *(float4*)&Bs[(rA + u * 32) * ALD + cA * 4] = w4;
        }
        __syncthreads();

        if (kt + 1 < KT) {
            int ko = (kt + 1) * 32 + cA * 4;
#pragma unroll
            for (int u = 0; u < 4; u++) aR[u] = *(const float4*)(arow[u] + ko);
#pragma unroll
            for (int u = 0; u < 3; u++) bR[u] = *(const float4*)(brow[u] + ko);
        }

#pragma unroll
        for (int kc = 0; kc < 4; kc++) {
            const int kk0 = kc * 8;
            uint32_t af[2][4];
#pragma unroll
            for (int i = 0; i < 2; i++) {
                int rm = m_off + i * 16;
                af[i][0] = __float_as_uint(As[(rm + grp) * ALD + kk0 + tq]);
                af[i][1] = __float_as_uint(As[(rm + 8 + grp) * ALD + kk0 + tq]);
                af[i][2] = __float_as_uint(As[(rm + grp) * ALD + kk0 + tq + 4]);
                af[i][3] = __float_as_uint(As[(rm + 8 + grp) * ALD + kk0 + tq + 4]);
            }
            uint32_t bfr[6][2];
#pragma unroll
            for (int j = 0; j < 6; j++) {
                int nb = n_off + j * 8;
                bfr[j][0] = __float_as_uint(Bs[(nb + grp) * ALD + kk0 + tq]);
                bfr[j][1] = __float_as_uint(Bs[(nb + grp) * ALD + kk0 + tq + 4]);
            }
#pragma unroll
            for (int i = 0; i < 2; i++)
#pragma unroll
                for (int j = 0; j < 6; j++) mma_tf32(acc[i][j], af[i], bfr[j]);
        }
    }

    // epilogue: bias + store (c0,c1 contiguous -> float2 stores)
#pragma unroll
    for (int j = 0; j < 6; j++) {
        int col = n0 + n_off + j * 8 + 2 * tq;
        float b0v = bias[col], b1v = bias[col + 1];
#pragma unroll
        for (int i = 0; i < 2; i++) {
            int rm = m0 + m_off + i * 16;
            float2 v0 = make_float2(acc[i][j][0] + b0v, acc[i][j][1] + b1v);
            float2 v1 = make_float2(acc[i][j][2] + b0v, acc[i][j][3] + b1v);
            *(float2*)&outp[(size_t)(rm + grp) * G3 + col] = v0;
            *(float2*)&outp[(size_t)(rm + 8 + grp) * G3 + col] = v1;
        }
    }
}

// ---------------------------------------------------------------------------
// K2/K4: GRU scan. grid=(64,2), 640 threads: thread = (g = tid>>2, b = tid&3).
//   Each thread computes all 3 gate dot-rows for its (g,b) -> local h update.
//   20 warps = exactly 5/SMSP (balanced fma); 4-lane weight dedup in smem.
// ---------------------------------------------------------------------------
__global__ __launch_bounds__(640)
void scan_kernel(const float* __restrict__ gi, const float* __restrict__ wp,
                 const float* __restrict__ bhf, const float* __restrict__ bhb,
                 float* __restrict__ yout, int layer) {
    extern __shared__ char smraw[];
    ulonglong2* ws = (ulonglong2*)smraw;                       // [SKQ*480]
    float* hbuf = (float*)(smraw + (size_t)SKQ * G3 * 16);     // [2][4][160]

    const int dir = blockIdx.y;
    const int b0 = blockIdx.x * 4;
    const int tid = threadIdx.x;
    const int g = tid >> 2;        // 0..159
    const int b = tid & 3;         // 0..3

    const ulonglong2* wsrc = (const ulonglong2*)wp + (size_t)(layer * 2 + dir) * 40 * G3;
    for (int i = tid; i < SKQ * G3; i += 640) ws[i] = wsrc[i];

    const float* bh = dir ? bhb : bhf;
    const float bhr = bh[g], bhz = bh[Hh + g], bhn = bh[2 * Hh + g];

    float hprev = 0.f;
    hbuf[b * Hh + g] = 0.f;
    __syncthreads();

    const float* gib = gi + (size_t)dir * Mrows * G3;
    int cur = 0;

    for (int s = 0; s < Tt; s++) {
        const int t = dir ? (Tt - 1 - s) : s;
        const float* gr = gib + ((size_t)t * Bb + b0 + b) * G3;

        // prefetch input gates (DRAM) - consumed after the dot loops
        float gir = gr[g], giz = gr[Hh + g], gin = gr[2 * Hh + g];

        u64 ar = 0ull, az = 0ull, an = 0ull;
        const float* hc = hbuf + cur * 640 + b * Hh;

        // ---- gmem-streamed kqs (SKQ..39), prefetch one ahead ----
        {
            ulonglong2 w0n = wsrc[SKQ * G3 + g];
            ulonglong2 w1n = wsrc[SKQ * G3 + Hh + g];
            ulonglong2 w2n = wsrc[SKQ * G3 + 2 * Hh + g];
#pragma unroll 2
            for (int kq = SKQ; kq < 40; kq++) {
                ulonglong2 w0 = w0n, w1 = w1n, w2 = w2n;
                if (kq < 39) {
                    int o = (kq + 1) * G3;
                    w0n = wsrc[o + g];
                    w1n = wsrc[o + Hh + g];
                    w2n = wsrc[o + 2 * Hh + g];
                }
                ulonglong2 hv = *(const ulonglong2*)&hc[kq * 4];
                fma2(ar, w0.x, hv.x); fma2(ar, w0.y, hv.y);
                fma2(az, w1.x, hv.x); fma2(az, w1.y, hv.y);
                fma2(an, w2.x, hv.x); fma2(an, w2.y, hv.y);
            }
        }
        // ---- smem-resident kqs (0..SKQ-1) ----
#pragma unroll 4
        for (int kq = 0; kq < SKQ; kq++) {
            ulonglong2 w0 = ws[kq * G3 + g];
            ulonglong2 w1 = ws[kq * G3 + Hh + g];
            ulonglong2 w2 = ws[kq * G3 + 2 * Hh + g];
            ulonglong2 hv = *(const ulonglong2*)&hc[kq * 4];
            fma2(ar, w0.x, hv.x); fma2(ar, w0.y, hv.y);
            fma2(az, w1.x, hv.x); fma2(az, w1.y, hv.y);
            fma2(an, w2.x, hv.x); fma2(an, w2.y, hv.y);
        }

        // ---- gate combine + h update (thread-local) ----
        float lr, hr, lz, hz, ln, hn;
        unpack2(ar, lr, hr);
        unpack2(az, lz, hz);
        unpack2(an, ln, hn);
        float r = sigm_f(gir + lr + hr + bhr);
        float z = sigm_f(giz + lz + hz + bhz);
        float n = tanhf(gin + r * (ln + hn + bhn));
        float hnew = (1.f - z) * n + z * hprev;
        hprev = hnew;
        hbuf[(cur ^ 1) * 640 + b * Hh + g] = hnew;
        if (layer == 0) {
            yout[((size_t)t * Bb + b0 + b) * 320 + dir * Hh + g] = hnew;
        }
        __syncthreads();
        cur ^= 1;
    }

    if (layer == 1) {
        yout[((size_t)dir * Bb + b0 + b) * Hh + g] = hprev;
    }
}

// ---------------------------------------------------------------------------
// K5: head
// ---------------------------------------------------------------------------
__global__ __launch_bounds__(128)
void head_kernel(const float* __restrict__ hfin,
                 const float* __restrict__ fc1w, const float* __restrict__ fc1b,
                 const float* __restrict__ fc2w, const float* __restrict__ fc2b,
                 float* __restrict__ out) {
    const int b = blockIdx.x;
    const int j = threadIdx.x;
    __shared__ float hv[320];
    __shared__ float red[4];

    for (int k = j; k < Hh; k += 128) {
        hv[k]      = hfin[(size_t)b * Hh + k];
        hv[Hh + k] = hfin[(size_t)Bb * Hh + (size_t)b * Hh + k];
    }
    __syncthreads();

    float acc = fc1b[j];
    const float* wr = fc1w + (size_t)j * 320;
#pragma unroll 8
    for (int k = 0; k < 320; k++) acc += wr[k] * hv[k];
    float v = fmaxf(acc, 0.f) * fc2w[j];

#pragma unroll
    for (int o = 16; o > 0; o >>= 1) v += __shfl_down_sync(0xffffffffu, v, o);
    if ((j & 31) == 0) red[j >> 5] = v;
    __syncthreads();
    if (j == 0) out[b] = red[0] + red[1] + red[2] + red[3] + fc2b[0];
}

// ---------------------------------------------------------------------------
// kernel_launch
// ---------------------------------------------------------------------------
extern "C" void kernel_launch(void* const* d_in, const int* in_sizes, int n_in,
                              void* d_out, int out_size) {
    const int*   x        = (const int*)  d_in[0];
    const float* emb      = (const float*)d_in[1];
    const float* Wih_l0f  = (const float*)d_in[2];
    const float* Whh_l0f  = (const float*)d_in[3];
    const float* bih_l0f  = (const float*)d_in[4];
    const float* bhh_l0f  = (const float*)d_in[5];
    const float* Wih_l0b  = (const float*)d_in[6];
    const float* Whh_l0b  = (const float*)d_in[7];
    const float* bih_l0b  = (const float*)d_in[8];
    const float* bhh_l0b  = (const float*)d_in[9];
    const float* Wih_l1f  = (const float*)d_in[10];
    const float* Whh_l1f  = (const float*)d_in[11];
    const float* bih_l1f  = (const float*)d_in[12];
    const float* bhh_l1f  = (const float*)d_in[13];
    const float* Wih_l1b  = (const float*)d_in[14];
    const float* Whh_l1b  = (const float*)d_in[15];
    const float* bih_l1b  = (const float*)d_in[16];
    const float* bhh_l1b  = (const float*)d_in[17];
    const float* fc1_w    = (const float*)d_in[18];
    const float* fc1_b    = (const float*)d_in[19];
    const float* fc2_w    = (const float*)d_in[20];
    const float* fc2_b    = (const float*)d_in[21];
    float* out = (float*)d_out;

    float *gi0, *gi1, *y0, *whhP, *hfin;
    cudaGetSymbolAddress((void**)&gi0,  g_gi0);
    cudaGetSymbolAddress((void**)&gi1,  g_gi1);
    cudaGetSymbolAddress((void**)&y0,   g_y0);
    cudaGetSymbolAddress((void**)&whhP, g_whhP);
    cudaGetSymbolAddress((void**)&hfin, g_hfin);

    static int smem_set = 0;
    const int scan_smem = SKQ * G3 * 16 + 2 * 640 * 4;   // 215040 + 5120 = 220160
    if (!smem_set) {
        cudaFuncSetAttribute(scan_kernel, cudaFuncAttributeMaxDynamicSharedMemorySize,
                             scan_smem);
        smem_set = 1;
    }

    pack_whh_kernel<<<4, 256>>>(Whh_l0f, Whh_l0b, Whh_l1f, Whh_l1b, whhP);

    {
        dim3 grid(Mrows / 128, G3 / 96, 2);
        gates_mma_kernel<128, true><<<grid, 256>>>(emb, x, Wih_l0f, Wih_l0b,
                                                   bih_l0f, bih_l0b, gi0);
    }

    scan_kernel<<<dim3(Bb / 4, 2), 640, scan_smem>>>(gi0, whhP, bhh_l0f, bhh_l0b, y0, 0);

    {
        dim3 grid(Mrows / 128, G3 / 96, 2);
        gates_mma_kernel<320, false><<<grid, 256>>>(y0, nullptr, Wih_l1f, Wih_l1b,
                                                    bih_l1f, bih_l1b, gi1);
    }

    scan_kernel<<<dim3(Bb / 4, 2), 640, scan_smem>>>(gi1, whhP, bhh_l1f, bhh_l1b, hfin, 1);

    head_kernel<<<Bb, 128>>>(hfin, fc1_w, fc1_b, fc2_w, fc2_b, out);
}

// round 4
// speedup vs baseline: 1.8165x; 1.8165x over previous
#include <cuda_runtime.h>
#include <math.h>
#include <stdint.h>

// ---------------------------------------------------------------------------
// TextGRUClassifier: 2-layer bidir GRU (B=256,T=512,E=128,H=160) + FC head
// R4: tf32 mma GEMMs (unchanged math, new gi/y0 layout [t][n][256]);
//     scan = 2-CTA cluster, each CTA holds HALF of Whh fully in smem (153.6KB),
//     h halves exchanged per step via st.shared::cluster + barrier.cluster.
// ---------------------------------------------------------------------------

#define Tt 512
#define Bb 256
#define Hh 160
#define G3 480
#define Mrows (Tt*Bb)     // 131072

typedef unsigned long long u64;

// ---- scratch ----
static __device__ float g_gi0[(size_t)2 * Mrows * G3];   // [dir][t][n=480][b=256]
static __device__ float g_gi1[(size_t)2 * Mrows * G3];
static __device__ float g_y0[(size_t)Mrows * 320];       // [t][n=320][b=256]
static __device__ float g_whhP[(size_t)8 * 40 * 240 * 4];// [dl*2+rank][kq][lr=240][4]
static __device__ float g_hfin[2 * Bb * Hh];             // [dir][b][g]

// ---- helpers ----
__device__ __forceinline__ void unpack2(u64 v, float& x, float& y) {
    asm("mov.b64 {%0, %1}, %2;" : "=f"(x), "=f"(y) : "l"(v));
}
__device__ __forceinline__ void fma2(u64& d, u64 a, u64 b) {
    asm("fma.rn.f32x2 %0, %1, %2, %0;" : "+l"(d) : "l"(a), "l"(b));
}
__device__ __forceinline__ float sigm_f(float x) { return 1.f / (1.f + __expf(-x)); }

__device__ __forceinline__ uint32_t f2tf32(float x) {
    uint32_t r;
    asm("cvt.rna.tf32.f32 %0, %1;" : "=r"(r) : "f"(x));
    return r;
}
__device__ __forceinline__ void mma_tf32(float* d, const uint32_t* a, const uint32_t* b) {
    asm volatile(
        "mma.sync.aligned.m16n8k8.row.col.f32.tf32.tf32.f32 "
        "{%0,%1,%2,%3}, {%4,%5,%6,%7}, {%8,%9}, {%0,%1,%2,%3};"
        : "+f"(d[0]), "+f"(d[1]), "+f"(d[2]), "+f"(d[3])
        : "r"(a[0]), "r"(a[1]), "r"(a[2]), "r"(a[3]), "r"(b[0]), "r"(b[1]));
}
__device__ __forceinline__ uint32_t smem_u32(const void* p) {
    uint32_t a;
    asm("{ .reg .u64 t; cvta.to.shared.u64 t, %1; cvt.u32.u64 %0, t; }" : "=r"(a) : "l"(p));
    return a;
}
__device__ __forceinline__ uint32_t mapa_peer(uint32_t addr, uint32_t rank) {
    uint32_t r;
    asm("mapa.shared::cluster.u32 %0, %1, %2;" : "=r"(r) : "r"(addr), "r"(rank));
    return r;
}
__device__ __forceinline__ void st_cluster_f32(uint32_t addr, float v) {
    asm volatile("st.shared::cluster.f32 [%0], %1;" :: "r"(addr), "f"(v) : "memory");
}
#define CLUSTER_SYNC() do { \
    asm volatile("barrier.cluster.arrive.aligned;" ::: "memory"); \
    asm volatile("barrier.cluster.wait.aligned;" ::: "memory"); \
} while (0)

// ---------------------------------------------------------------------------
// K0: pack Whh[row=gate*160+gg][k] -> whhP[(dl*2+rank)][k>>2][gate*80+gg%80][k&3]
// ---------------------------------------------------------------------------
__global__ void pack_whh_kernel(const float* __restrict__ w0f, const float* __restrict__ w0b,
                                const float* __restrict__ w1f, const float* __restrict__ w1b,
                                float* __restrict__ wp) {
    int dl = blockIdx.x;
    const float* w = (dl == 0) ? w0f : (dl == 1) ? w0b : (dl == 2) ? w1f : w1b;
    for (int i = threadIdx.x; i < G3 * Hh; i += blockDim.x) {
        int row = i / Hh, k = i % Hh;
        int gate = row / Hh;                 // 0..2  (row = gate*160 + gg)
        int gg = row - gate * Hh;            // 0..159
        int rank = (gg >= 80) ? 1 : 0;
        int lr = gate * 80 + (gg - rank * 80);
        wp[((((size_t)dl * 2 + rank) * 40 + (k >> 2)) * 240 + lr) * 4 + (k & 3)] = w[i];
    }
}

// ---------------------------------------------------------------------------
// K1/K3: gates GEMM on tf32 tensor cores.
//   out layout: [dir][t][n=480][b=256].
//   GATHER (layer0): A = emb rows via x.  Non-gather (layer1): A = y0 [t][k][256].
// ---------------------------------------------------------------------------
#define ALD 36    // [m][k] padded stride (GATHER path)
#define MLD 136   // [k][m] padded stride (layer-1 path)

template <int KDIM, bool GATHER>
__global__ __launch_bounds__(256, 2)
void gates_mma_kernel(const float* __restrict__ A, const int* __restrict__ xids,
                      const float* __restrict__ Wf, const float* __restrict__ Wb,
                      const float* __restrict__ bf, const float* __restrict__ bb,
                      float* __restrict__ out) {
    const int m0 = blockIdx.x * 128;
    const int n0 = blockIdx.y * 96;
    const int dir = blockIdx.z;
    const float* W = dir ? Wb : Wf;
    const float* bias = dir ? bb : bf;
    float* outp = out + (size_t)dir * Mrows * G3;

    __shared__ float As[128 * ALD];   // GATHER: [m][ALD]; else [k][MLD] (4352 <= 4608)
    __shared__ float Bs[96 * ALD];    // [n][k]
    __shared__ int rid[128];

    const int tid = threadIdx.x;
    if (GATHER) {
        if (tid < 128) {
            int m = m0 + tid;
            rid[tid] = xids[(m & 255) * Tt + (m >> 8)];
        }
        __syncthreads();
    }

    const int lane = tid & 31, wid = tid >> 5;
    const int grp = lane >> 2, tq = lane & 3;
    const int m_off = (wid >> 1) * 32;
    const int n_off = (wid & 1) * 48;

    float acc[2][6][4];
#pragma unroll
    for (int i = 0; i < 2; i++)
#pragma unroll
        for (int j = 0; j < 6; j++)
#pragma unroll
            for (int c = 0; c < 4; c++) acc[i][j][c] = 0.f;

    // ---- A staging coordinates ----
    // GATHER: idx = tid (+u*256): row = idx>>3 (0..127? rA+u*32), kquad = tid&7
    const int rA = tid >> 3;      // 0..31
    const int cA = tid & 7;       // 0..7
    const float* arow[4];
    if (GATHER) {
#pragma unroll
        for (int u = 0; u < 4; u++) arow[u] = A + (size_t)rid[rA + u * 32] * KDIM;
    }
    // layer1: A is [t][k][256]; tile t fixed.
    const float* Abase = GATHER ? nullptr
                        : A + ((size_t)(m0 >> 8) * KDIM) * 256 + (m0 & 255);
    const int kL = tid >> 3;          // wait: need idx>>5 per-u; compute inline below
    (void)kL;

    const float* brow[3];
#pragma unroll
    for (int u = 0; u < 3; u++) brow[u] = W + (size_t)(n0 + rA + u * 32) * KDIM;

    const int KT = KDIM / 32;
    float4 aR[4], bR[3];

    // prologue load tile 0
    if (GATHER) {
#pragma unroll
        for (int u = 0; u < 4; u++) aR[u] = *(const float4*)(arow[u] + cA * 4);
    } else {
#pragma unroll
        for (int u = 0; u < 4; u++) {
            int idx = u * 256 + tid;
            int k = idx >> 5, m4 = (idx & 31) * 4;
            aR[u] = *(const float4*)(Abase + (size_t)k * 256 + m4);
        }
    }
#pragma unroll
    for (int u = 0; u < 3; u++) bR[u] = *(const float4*)(brow[u] + cA * 4);

    for (int kt = 0; kt < KT; kt++) {
        __syncthreads();
        if (GATHER) {
#pragma unroll
            for (int u = 0; u < 4; u++) {
                float4 v = aR[u];
                float4 w4 = make_float4(__uint_as_float(f2tf32(v.x)), __uint_as_float(f2tf32(v.y)),
                                        __uint_as_float(f2tf32(v.z)), __uint_as_float(f2tf32(v.w)));
                *(float4*)&As[(rA + u * 32) * ALD + cA * 4] = w4;
            }
        } else {
#pragma unroll
            for (int u = 0; u < 4; u++) {
                int idx = u * 256 + tid;
                int k = idx >> 5, m4 = (idx & 31) * 4;
                float4 v = aR[u];
                float4 w4 = make_float4(__uint_as_float(f2tf32(v.x)), __uint_as_float(f2tf32(v.y)),
                                        __uint_as_float(f2tf32(v.z)), __uint_as_float(f2tf32(v.w)));
                *(float4*)&As[k * MLD + m4] = w4;
            }
        }
#pragma unroll
        for (int u = 0; u < 3; u++) {
            float4 v = bR[u];
            float4 w4 = make_float4(__uint_as_float(f2tf32(v.x)), __uint_as_float(f2tf32(v.y)),
                                    __uint_as_float(f2tf32(v.z)), __uint_as_float(f2tf32(v.w)));
            *(float4*)&Bs[(rA + u * 32) * ALD + cA * 4] = w4;
        }
        __syncthreads();

        if (kt + 1 < KT) {
            int ko = (kt + 1) * 32;
            if (GATHER) {
#pragma unroll
                for (int u = 0; u < 4; u++) aR[u] = *(const float4*)(arow[u] + ko + cA * 4);
            } else {
#pragma unroll
                for (int u = 0; u < 4; u++) {
                    int idx = u * 256 + tid;
                    int k = idx >> 5, m4 = (idx & 31) * 4;
                    aR[u] = *(const float4*)(Abase + (size_t)(ko + k) * 256 + m4);
                }
            }
#pragma unroll
            for (int u = 0; u < 3; u++) bR[u] = *(const float4*)(brow[u] + ko + cA * 4);
        }

#pragma unroll
        for (int kc = 0; kc < 4; kc++) {
            const int kk0 = kc * 8;
            uint32_t af[2][4];
            if (GATHER) {
#pragma unroll
                for (int i = 0; i < 2; i++) {
                    int rm = m_off + i * 16;
                    af[i][0] = __float_as_uint(As[(rm + grp) * ALD + kk0 + tq]);
                    af[i][1] = __float_as_uint(As[(rm + 8 + grp) * ALD + kk0 + tq]);
                    af[i][2] = __float_as_uint(As[(rm + grp) * ALD + kk0 + tq + 4]);
                    af[i][3] = __float_as_uint(As[(rm + 8 + grp) * ALD + kk0 + tq + 4]);
                }
            } else {
#pragma unroll
                for (int i = 0; i < 2; i++) {
                    int rm = m_off + i * 16;
                    af[i][0] = __float_as_uint(As[(kk0 + tq) * MLD + rm + grp]);
                    af[i][1] = __float_as_uint(As[(kk0 + tq) * MLD + rm + 8 + grp]);
                    af[i][2] = __float_as_uint(As[(kk0 + tq + 4) * MLD + rm + grp]);
                    af[i][3] = __float_as_uint(As[(kk0 + tq + 4) * MLD + rm + 8 + grp]);
                }
            }
            uint32_t bfr[6][2];
#pragma unroll
            for (int j = 0; j < 6; j++) {
                int nb = n_off + j * 8;
                bfr[j][0] = __float_as_uint(Bs[(nb + grp) * ALD + kk0 + tq]);
                bfr[j][1] = __float_as_uint(Bs[(nb + grp) * ALD + kk0 + tq + 4]);
            }
#pragma unroll
            for (int i = 0; i < 2; i++)
#pragma unroll
                for (int j = 0; j < 6; j++) mma_tf32(acc[i][j], af[i], bfr[j]);
        }
    }

    // epilogue -> out[t][n][256]: addr = t*480*256 + n*256 + b
    {
        const int t_t = m0 >> 8;
        const int bb = m0 & 255;
        float* ob = outp + (size_t)t_t * G3 * 256 + bb;
#pragma unroll
        for (int j = 0; j < 6; j++) {
            int col = n0 + n_off + j * 8 + 2 * tq;
            float b0v = bias[col], b1v = bias[col + 1];
#pragma unroll
            for (int i = 0; i < 2; i++) {
                int ml = m_off + i * 16 + grp;
                ob[(size_t)col * 256 + ml]           = acc[i][j][0] + b0v;
                ob[(size_t)(col + 1) * 256 + ml]     = acc[i][j][1] + b1v;
                ob[(size_t)col * 256 + ml + 8]       = acc[i][j][2] + b0v;
                ob[(size_t)(col + 1) * 256 + ml + 8] = acc[i][j][3] + b1v;
            }
        }
    }
}

// ---------------------------------------------------------------------------
// K2/K4: GRU scan, 2-CTA cluster. grid=(64,2): x = chunk*2 + rank, y = dir.
//   CTA rank r: g in [r*80, r*80+80), 640 thr = 80 g x 8 b. ALL its Whh rows
//   (240 x 160 fp32 = 153.6KB) live in smem. Per step: dot from hbuf[cur],
//   gate math, write hnew locally + to peer via st.shared::cluster, cluster sync.
// ---------------------------------------------------------------------------
#define HST 164                       // padded h row stride (floats)
#define HBUFN (8 * HST)               // floats per buffer
#define WS_BYTES (40 * 240 * 16)      // 153600

__global__ __launch_bounds__(640) __cluster_dims__(2, 1, 1)
void scan_kernel(const float* __restrict__ gi, const float* __restrict__ wp,
                 const float* __restrict__ bhf, const float* __restrict__ bhb,
                 float* __restrict__ yout, int layer) {
    extern __shared__ __align__(16) char smraw[];
    ulonglong2* ws = (ulonglong2*)smraw;                 // [40*240]
    float* hbuf = (float*)(smraw + WS_BYTES);            // [2][8][HST]

    const int dir = blockIdx.y;
    const int rank = blockIdx.x & 1;
    const int b0 = (blockIdx.x >> 1) * 8;
    const int tid = threadIdx.x;
    const int g_loc = tid >> 3;        // 0..79
    const int b = tid & 7;             // 0..7
    const int g = rank * 80 + g_loc;   // 0..159

    // load this CTA's Whh slice into smem (coalesced)
    const ulonglong2* wsrc = (const ulonglong2*)wp +
                             (size_t)((layer * 2 + dir) * 2 + rank) * 40 * 240;
    for (int i = tid; i < 40 * 240; i += 640) ws[i] = wsrc[i];

    const float* bh = dir ? bhb : bhf;
    const float bhr = bh[g], bhz = bh[Hh + g], bhn = bh[2 * Hh + g];

    // zero both h buffers
    for (int i = tid; i < 2 * HBUFN; i += 640) hbuf[i] = 0.f;

    // peer address for my h slot (same offset each step; two buffers)
    const uint32_t my0 = smem_u32(&hbuf[b * HST + g]);
    const uint32_t my1 = smem_u32(&hbuf[HBUFN + b * HST + g]);
    const uint32_t pr0 = mapa_peer(my0, rank ^ 1);
    const uint32_t pr1 = mapa_peer(my1, rank ^ 1);

    float hprev = 0.f;
    __syncthreads();
    CLUSTER_SYNC();   // smem init visible cluster-wide before any peer store

    const float* gib = gi + (size_t)dir * Mrows * G3;
    int cur = 0;

    for (int s = 0; s < Tt; s++) {
        const int t = dir ? (Tt - 1 - s) : s;
        const float* gr = gib + (size_t)t * G3 * 256 + b0 + b;

        // prefetch input gates (coalesced in b)
        float gir = gr[(size_t)g * 256];
        float giz = gr[(size_t)(Hh + g) * 256];
        float gin = gr[(size_t)(2 * Hh + g) * 256];

        u64 ar = 0ull, az = 0ull, an = 0ull;
        const float* hc = hbuf + cur * HBUFN + b * HST;

#pragma unroll 5
        for (int kq = 0; kq < 40; kq++) {
            ulonglong2 hv = *(const ulonglong2*)(hc + kq * 4);
            ulonglong2 w0 = ws[kq * 240 + g_loc];
            ulonglong2 w1 = ws[kq * 240 + 80 + g_loc];
            ulonglong2 w2 = ws[kq * 240 + 160 + g_loc];
            fma2(ar, w0.x, hv.x); fma2(ar, w0.y, hv.y);
            fma2(az, w1.x, hv.x); fma2(az, w1.y, hv.y);
            fma2(an, w2.x, hv.x); fma2(an, w2.y, hv.y);
        }

        float lr, hr, lz, hz, ln, hn;
        unpack2(ar, lr, hr);
        unpack2(az, lz, hz);
        unpack2(an, ln, hn);
        float r = sigm_f(gir + lr + hr + bhr);
        float z = sigm_f(giz + lz + hz + bhz);
        float n = tanhf(gin + r * (ln + hn + bhn));
        float hnew = (1.f - z) * n + z * hprev;
        hprev = hnew;

        const int nxt = cur ^ 1;
        hbuf[nxt * HBUFN + b * HST + g] = hnew;           // local
        st_cluster_f32(nxt ? pr1 : pr0, hnew);            // peer

        if (layer == 0) {
            yout[((size_t)t * 320 + dir * Hh + g) * 256 + b0 + b] = hnew;
        }

        CLUSTER_SYNC();   // release my stores / acquire peer's
        cur = nxt;
    }

    if (layer == 1) {
        yout[((size_t)(dir * Bb + b0 + b)) * Hh + g] = hprev;
    }
}

// ---------------------------------------------------------------------------
// K5: head
// ---------------------------------------------------------------------------
__global__ __launch_bounds__(128)
void head_kernel(const float* __restrict__ hfin,
                 const float* __restrict__ fc1w, const float* __restrict__ fc1b,
                 const float* __restrict__ fc2w, const float* __restrict__ fc2b,
                 float* __restrict__ out) {
    const int b = blockIdx.x;
    const int j = threadIdx.x;
    __shared__ float hv[320];
    __shared__ float red[4];

    for (int k = j; k < Hh; k += 128) {
        hv[k]      = hfin[(size_t)b * Hh + k];
        hv[Hh + k] = hfin[(size_t)Bb * Hh + (size_t)b * Hh + k];
    }
    __syncthreads();

    float acc = fc1b[j];
    const float* wr = fc1w + (size_t)j * 320;
#pragma unroll 8
    for (int k = 0; k < 320; k++) acc += wr[k] * hv[k];
    float v = fmaxf(acc, 0.f) * fc2w[j];

#pragma unroll
    for (int o = 16; o > 0; o >>= 1) v += __shfl_down_sync(0xffffffffu, v, o);
    if ((j & 31) == 0) red[j >> 5] = v;
    __syncthreads();
    if (j == 0) out[b] = red[0] + red[1] + red[2] + red[3] + fc2b[0];
}

// ---------------------------------------------------------------------------
// kernel_launch
// ---------------------------------------------------------------------------
extern "C" void kernel_launch(void* const* d_in, const int* in_sizes, int n_in,
                              void* d_out, int out_size) {
    const int*   x        = (const int*)  d_in[0];
    const float* emb      = (const float*)d_in[1];
    const float* Wih_l0f  = (const float*)d_in[2];
    const float* Whh_l0f  = (const float*)d_in[3];
    const float* bih_l0f  = (const float*)d_in[4];
    const float* bhh_l0f  = (const float*)d_in[5];
    const float* Wih_l0b  = (const float*)d_in[6];
    const float* Whh_l0b  = (const float*)d_in[7];
    const float* bih_l0b  = (const float*)d_in[8];
    const float* bhh_l0b  = (const float*)d_in[9];
    const float* Wih_l1f  = (const float*)d_in[10];
    const float* Whh_l1f  = (const float*)d_in[11];
    const float* bih_l1f  = (const float*)d_in[12];
    const float* bhh_l1f  = (const float*)d_in[13];
    const float* Wih_l1b  = (const float*)d_in[14];
    const float* Whh_l1b  = (const float*)d_in[15];
    const float* bih_l1b  = (const float*)d_in[16];
    const float* bhh_l1b  = (const float*)d_in[17];
    const float* fc1_w    = (const float*)d_in[18];
    const float* fc1_b    = (const float*)d_in[19];
    const float* fc2_w    = (const float*)d_in[20];
    const float* fc2_b    = (const float*)d_in[21];
    float* out = (float*)d_out;

    float *gi0, *gi1, *y0, *whhP, *hfin;
    cudaGetSymbolAddress((void**)&gi0,  g_gi0);
    cudaGetSymbolAddress((void**)&gi1,  g_gi1);
    cudaGetSymbolAddress((void**)&y0,   g_y0);
    cudaGetSymbolAddress((void**)&whhP, g_whhP);
    cudaGetSymbolAddress((void**)&hfin, g_hfin);

    static int smem_set = 0;
    const int scan_smem = WS_BYTES + 2 * HBUFN * 4;   // 153600 + 5248 = 158848
    if (!smem_set) {
        cudaFuncSetAttribute(scan_kernel, cudaFuncAttributeMaxDynamicSharedMemorySize,
                             scan_smem);
        smem_set = 1;
    }

    pack_whh_kernel<<<4, 512>>>(Whh_l0f, Whh_l0b, Whh_l1f, Whh_l1b, whhP);

    {
        dim3 grid(Mrows / 128, G3 / 96, 2);
        gates_mma_kernel<128, true><<<grid, 256>>>(emb, x, Wih_l0f, Wih_l0b,
                                                   bih_l0f, bih_l0b, gi0);
    }

    scan_kernel<<<dim3(64, 2), 640, scan_smem>>>(gi0, whhP, bhh_l0f, bhh_l0b, y0, 0);

    {
        dim3 grid(Mrows / 128, G3 / 96, 2);
        gates_mma_kernel<320, false><<<grid, 256>>>(y0, nullptr, Wih_l1f, Wih_l1b,
                                                    bih_l1f, bih_l1b, gi1);
    }

    scan_kernel<<<dim3(64, 2), 640, scan_smem>>>(gi1, whhP, bhh_l1f, bhh_l1b, hfin, 1);

    head_kernel<<<Bb, 128>>>(hfin, fc1_w, fc1_b, fc2_w, fc2_b, out);
}

// round 5
// speedup vs baseline: 3.8325x; 2.1099x over previous
#include <cuda_runtime.h>
#include <math.h>
#include <stdint.h>

// ---------------------------------------------------------------------------
// TextGRUClassifier: 2-layer bidir GRU (B=256,T=512,E=128,H=160) + FC head
// R5: gates GEMMs on tf32 mma (unchanged from R4). Scan h-dot ALSO on tf32
//     mma.sync: 2-CTA cluster, 240 gate rows/CTA, Whh fragments preloaded in
//     REGISTERS (80 regs/thread), gh exchanged via smem fragments, h halves
//     exchanged via st.shared::cluster + split cluster barrier.
// ---------------------------------------------------------------------------

#define Tt 512
#define Bb 256
#define Hh 160
#define G3 480
#define Mrows (Tt*Bb)     // 131072

typedef unsigned long long u64;

// ---- scratch ----
static __device__ float g_gi0[(size_t)2 * Mrows * G3];   // [dir][t][n=480][b=256]
static __device__ float g_gi1[(size_t)2 * Mrows * G3];
static __device__ float g_y0[(size_t)Mrows * 320];       // [t][n=320][b=256]
static __device__ float g_hfin[2 * Bb * Hh];             // [dir][b][g]

// ---- helpers ----
__device__ __forceinline__ float sigm_f(float x) { return 1.f / (1.f + __expf(-x)); }

__device__ __forceinline__ uint32_t f2tf32(float x) {
    uint32_t r;
    asm("cvt.rna.tf32.f32 %0, %1;" : "=r"(r) : "f"(x));
    return r;
}
__device__ __forceinline__ void mma_tf32(float* d, const uint32_t* a, const uint32_t* b) {
    asm volatile(
        "mma.sync.aligned.m16n8k8.row.col.f32.tf32.tf32.f32 "
        "{%0,%1,%2,%3}, {%4,%5,%6,%7}, {%8,%9}, {%0,%1,%2,%3};"
        : "+f"(d[0]), "+f"(d[1]), "+f"(d[2]), "+f"(d[3])
        : "r"(a[0]), "r"(a[1]), "r"(a[2]), "r"(a[3]), "r"(b[0]), "r"(b[1]));
}
__device__ __forceinline__ uint32_t smem_u32(const void* p) {
    uint32_t a;
    asm("{ .reg .u64 t; cvta.to.shared.u64 t, %1; cvt.u32.u64 %0, t; }" : "=r"(a) : "l"(p));
    return a;
}
__device__ __forceinline__ uint32_t mapa_peer(uint32_t addr, uint32_t rank) {
    uint32_t r;
    asm("mapa.shared::cluster.u32 %0, %1, %2;" : "=r"(r) : "r"(addr), "r"(rank));
    return r;
}
__device__ __forceinline__ void st_cluster_f32(uint32_t addr, float v) {
    asm volatile("st.shared::cluster.f32 [%0], %1;" :: "r"(addr), "f"(v) : "memory");
}
#define CLUSTER_ARRIVE() asm volatile("barrier.cluster.arrive.aligned;" ::: "memory")
#define CLUSTER_WAIT()   asm volatile("barrier.cluster.wait.aligned;" ::: "memory")

// ---------------------------------------------------------------------------
// K1/K3: gates GEMM on tf32 tensor cores (unchanged from R4).
//   out layout: [dir][t][n=480][b=256].
// ---------------------------------------------------------------------------
#define ALD 36
#define MLD 136

template <int KDIM, bool GATHER>
__global__ __launch_bounds__(256, 2)
void gates_mma_kernel(const float* __restrict__ A, const int* __restrict__ xids,
                      const float* __restrict__ Wf, const float* __restrict__ Wb,
                      const float* __restrict__ bf, const float* __restrict__ bb,
                      float* __restrict__ out) {
    const int m0 = blockIdx.x * 128;
    const int n0 = blockIdx.y * 96;
    const int dir = blockIdx.z;
    const float* W = dir ? Wb : Wf;
    const float* bias = dir ? bb : bf;
    float* outp = out + (size_t)dir * Mrows * G3;

    __shared__ float As[128 * ALD];
    __shared__ float Bs[96 * ALD];
    __shared__ int rid[128];

    const int tid = threadIdx.x;
    if (GATHER) {
        if (tid < 128) {
            int m = m0 + tid;
            rid[tid] = xids[(m & 255) * Tt + (m >> 8)];
        }
        __syncthreads();
    }

    const int lane = tid & 31, wid = tid >> 5;
    const int grp = lane >> 2, tq = lane & 3;
    const int m_off = (wid >> 1) * 32;
    const int n_off = (wid & 1) * 48;

    float acc[2][6][4];
#pragma unroll
    for (int i = 0; i < 2; i++)
#pragma unroll
        for (int j = 0; j < 6; j++)
#pragma unroll
            for (int c = 0; c < 4; c++) acc[i][j][c] = 0.f;

    const int rA = tid >> 3;
    const int cA = tid & 7;
    const float* arow[4];
    if (GATHER) {
#pragma unroll
        for (int u = 0; u < 4; u++) arow[u] = A + (size_t)rid[rA + u * 32] * KDIM;
    }
    const float* Abase = GATHER ? nullptr
                        : A + ((size_t)(m0 >> 8) * KDIM) * 256 + (m0 & 255);

    const float* brow[3];
#pragma unroll
    for (int u = 0; u < 3; u++) brow[u] = W + (size_t)(n0 + rA + u * 32) * KDIM;

    const int KT = KDIM / 32;
    float4 aR[4], bR[3];

    if (GATHER) {
#pragma unroll
        for (int u = 0; u < 4; u++) aR[u] = *(const float4*)(arow[u] + cA * 4);
    } else {
#pragma unroll
        for (int u = 0; u < 4; u++) {
            int idx = u * 256 + tid;
            int k = idx >> 5, m4 = (idx & 31) * 4;
            aR[u] = *(const float4*)(Abase + (size_t)k * 256 + m4);
        }
    }
#pragma unroll
    for (int u = 0; u < 3; u++) bR[u] = *(const float4*)(brow[u] + cA * 4);

    for (int kt = 0; kt < KT; kt++) {
        __syncthreads();
        if (GATHER) {
#pragma unroll
            for (int u = 0; u < 4; u++) {
                float4 v = aR[u];
                float4 w4 = make_float4(__uint_as_float(f2tf32(v.x)), __uint_as_float(f2tf32(v.y)),
                                        __uint_as_float(f2tf32(v.z)), __uint_as_float(f2tf32(v.w)));
                *(float4*)&As[(rA + u * 32) * ALD + cA * 4] = w4;
            }
        } else {
#pragma unroll
            for (int u = 0; u < 4; u++) {
                int idx = u * 256 + tid;
                int k = idx >> 5, m4 = (idx & 31) * 4;
                float4 v = aR[u];
                float4 w4 = make_float4(__uint_as_float(f2tf32(v.x)), __uint_as_float(f2tf32(v.y)),
                                        __uint_as_float(f2tf32(v.z)), __uint_as_float(f2tf32(v.w)));
                *(float4*)&As[k * MLD + m4] = w4;
            }
        }
#pragma unroll
        for (int u = 0; u < 3; u++) {
            float4 v = bR[u];
            float4 w4 = make_float4(__uint_as_float(f2tf32(v.x)), __uint_as_float(f2tf32(v.y)),
                                    __uint_as_float(f2tf32(v.z)), __uint_as_float(f2tf32(v.w)));
            *(float4*)&Bs[(rA + u * 32) * ALD + cA * 4] = w4;
        }
        __syncthreads();

        if (kt + 1 < KT) {
            int ko = (kt + 1) * 32;
            if (GATHER) {
#pragma unroll
                for (int u = 0; u < 4; u++) aR[u] = *(const float4*)(arow[u] + ko + cA * 4);
            } else {
#pragma unroll
                for (int u = 0; u < 4; u++) {
                    int idx = u * 256 + tid;
                    int k = idx >> 5, m4 = (idx & 31) * 4;
                    aR[u] = *(const float4*)(Abase + (size_t)(ko + k) * 256 + m4);
                }
            }
#pragma unroll
            for (int u = 0; u < 3; u++) bR[u] = *(const float4*)(brow[u] + ko + cA * 4);
        }

#pragma unroll
        for (int kc = 0; kc < 4; kc++) {
            const int kk0 = kc * 8;
            uint32_t af[2][4];
            if (GATHER) {
#pragma unroll
                for (int i = 0; i < 2; i++) {
                    int rm = m_off + i * 16;
                    af[i][0] = __float_as_uint(As[(rm + grp) * ALD + kk0 + tq]);
                    af[i][1] = __float_as_uint(As[(rm + 8 + grp) * ALD + kk0 + tq]);
                    af[i][2] = __float_as_uint(As[(rm + grp) * ALD + kk0 + tq + 4]);
                    af[i][3] = __float_as_uint(As[(rm + 8 + grp) * ALD + kk0 + tq + 4]);
                }
            } else {
#pragma unroll
                for (int i = 0; i < 2; i++) {
                    int rm = m_off + i * 16;
                    af[i][0] = __float_as_uint(As[(kk0 + tq) * MLD + rm + grp]);
                    af[i][1] = __float_as_uint(As[(kk0 + tq) * MLD + rm + 8 + grp]);
                    af[i][2] = __float_as_uint(As[(kk0 + tq + 4) * MLD + rm + grp]);
                    af[i][3] = __float_as_uint(As[(kk0 + tq + 4) * MLD + rm + 8 + grp]);
                }
            }
            uint32_t bfr[6][2];
#pragma unroll
            for (int j = 0; j < 6; j++) {
                int nb = n_off + j * 8;
                bfr[j][0] = __float_as_uint(Bs[(nb + grp) * ALD + kk0 + tq]);
                bfr[j][1] = __float_as_uint(Bs[(nb + grp) * ALD + kk0 + tq + 4]);
            }
#pragma unroll
            for (int i = 0; i < 2; i++)
#pragma unroll
                for (int j = 0; j < 6; j++) mma_tf32(acc[i][j], af[i], bfr[j]);
        }
    }

    {
        const int t_t = m0 >> 8;
        const int bb = m0 & 255;
        float* ob = outp + (size_t)t_t * G3 * 256 + bb;
#pragma unroll
        for (int j = 0; j < 6; j++) {
            int col = n0 + n_off + j * 8 + 2 * tq;
            float b0v = bias[col], b1v = bias[col + 1];
#pragma unroll
            for (int i = 0; i < 2; i++) {
                int ml = m_off + i * 16 + grp;
                ob[(size_t)col * 256 + ml]           = acc[i][j][0] + b0v;
                ob[(size_t)(col + 1) * 256 + ml]     = acc[i][j][1] + b1v;
                ob[(size_t)col * 256 + ml + 8]       = acc[i][j][2] + b0v;
                ob[(size_t)(col + 1) * 256 + ml + 8] = acc[i][j][3] + b1v;
            }
        }
    }
}

// ---------------------------------------------------------------------------
// K2/K4: GRU scan on tensor cores. 2-CTA cluster, grid=(64,2):
//   x = chunk*2 + rank, y = dir. CTA rank r owns units [r*80, r*80+80)
//   = 240 gate rows = 15 m16-tiles. 512 threads; warps 0..14 each own one
//   m16-tile, Whh A-fragments (20 k-tiles x 4 regs) preloaded in registers.
//   Per step: mma gh = Whh_slice @ h (n=8 batch), scatter gh frags -> smem,
//   gate combine on 640 (u,b) items, h halves pushed to peer CTA.
// ---------------------------------------------------------------------------
#define HST 172                  // h row stride (floats): 172%32=12 -> conflict-free frags
#define HBUFN (8 * HST)

__global__ __launch_bounds__(512) __cluster_dims__(2, 1, 1)
void scan_mma_kernel(const float* __restrict__ gi,
                     const float* __restrict__ whhF, const float* __restrict__ whhB,
                     const float* __restrict__ bhf, const float* __restrict__ bhb,
                     float* __restrict__ yout, int layer) {
    __shared__ float hbuf[2][HBUFN];   // [buf][b][k(g)]
    __shared__ float gh[240 * 8];      // [lr][b]

    const int dir = blockIdx.y;
    const int rank = blockIdx.x & 1;
    const int b0 = (blockIdx.x >> 1) * 8;
    const int tid = threadIdx.x;
    const int wid = tid >> 5, lane = tid & 31;
    const int grp = lane >> 2, tq = lane & 3;

    // ---- preload Whh A-fragments into registers (tf32-rounded) ----
    uint32_t wreg[80];
    const bool is_mma = (wid < 15);
    if (is_mma) {
        const int gate = wid / 5, mseg = wid % 5;
        const int gr0 = gate * Hh + rank * 80 + mseg * 16 + grp;   // global Whh row
        const float* W = dir ? whhB : whhF;
#pragma unroll
        for (int kt = 0; kt < 20; kt++) {
            wreg[kt * 4 + 0] = f2tf32(W[(size_t)gr0 * Hh + kt * 8 + tq]);
            wreg[kt * 4 + 1] = f2tf32(W[(size_t)(gr0 + 8) * Hh + kt * 8 + tq]);
            wreg[kt * 4 + 2] = f2tf32(W[(size_t)gr0 * Hh + kt * 8 + tq + 4]);
            wreg[kt * 4 + 3] = f2tf32(W[(size_t)(gr0 + 8) * Hh + kt * 8 + tq + 4]);
        }
    }

    // ---- combine-item setup: item A = (uA = tid>>3, bA = tid&7);
    //      item B (tid<128) = (uB = 64 + tid>>3, same bA) ----
    const int uA = tid >> 3, bA = tid & 7;
    const int gA = rank * 80 + uA;
    const float* bh = dir ? bhb : bhf;
    const float bhrA = bh[gA], bhzA = bh[Hh + gA], bhnA = bh[2 * Hh + gA];
    const float* gib = gi + (size_t)dir * Mrows * G3;
    const float* giA = gib + (size_t)gA * 256 + b0 + bA;
    uint32_t prA[2];
    prA[0] = mapa_peer(smem_u32(&hbuf[0][bA * HST + gA]), rank ^ 1);
    prA[1] = mapa_peer(smem_u32(&hbuf[1][bA * HST + gA]), rank ^ 1);

    const bool hasB = (tid < 128);
    const int uB = 64 + (tid >> 3), gB = rank * 80 + uB;
    float bhrB = 0.f, bhzB = 0.f, bhnB = 0.f;
    const float* giB = giA;
    uint32_t prB[2] = {0u, 0u};
    if (hasB) {
        bhrB = bh[gB]; bhzB = bh[Hh + gB]; bhnB = bh[2 * Hh + gB];
        giB = gib + (size_t)gB * 256 + b0 + bA;
        prB[0] = mapa_peer(smem_u32(&hbuf[0][bA * HST + gB]), rank ^ 1);
        prB[1] = mapa_peer(smem_u32(&hbuf[1][bA * HST + gB]), rank ^ 1);
    }

    for (int i = tid; i < 2 * HBUFN; i += 512) (&hbuf[0][0])[i] = 0.f;
    __syncthreads();
    CLUSTER_ARRIVE();   // release zero-init

    float hA = 0.f, hB = 0.f;
    int cur = 0;

    for (int s = 0; s < Tt; s++) {
        const int t = dir ? (Tt - 1 - s) : s;
        const size_t toff = (size_t)t * G3 * 256;

        // issue gi loads before blocking on the cluster barrier (hides DRAM)
        float girA = giA[toff], gizA = giA[toff + (size_t)Hh * 256],
              ginA = giA[toff + (size_t)2 * Hh * 256];
        float girB = 0.f, gizB = 0.f, ginB = 0.f;
        if (hasB) {
            girB = giB[toff]; gizB = giB[toff + (size_t)Hh * 256];
            ginB = giB[toff + (size_t)2 * Hh * 256];
        }

        CLUSTER_WAIT();   // acquire: both CTAs' h stores for hbuf[cur] visible

        if (is_mma) {
            const float* hc = hbuf[cur];
            float acc0[4] = {0.f, 0.f, 0.f, 0.f};
            float acc1[4] = {0.f, 0.f, 0.f, 0.f};
#pragma unroll
            for (int kt = 0; kt < 20; kt += 2) {
                uint32_t bfr[2];
                bfr[0] = f2tf32(hc[grp * HST + kt * 8 + tq]);
                bfr[1] = f2tf32(hc[grp * HST + kt * 8 + tq + 4]);
                mma_tf32(acc0, &wreg[kt * 4], bfr);
                uint32_t bfr2[2];
                bfr2[0] = f2tf32(hc[grp * HST + (kt + 1) * 8 + tq]);
                bfr2[1] = f2tf32(hc[grp * HST + (kt + 1) * 8 + tq + 4]);
                mma_tf32(acc1, &wreg[(kt + 1) * 4], bfr2);
            }
            const int lr = wid * 16;
            *(float2*)&gh[(lr + grp) * 8 + 2 * tq] =
                make_float2(acc0[0] + acc1[0], acc0[1] + acc1[1]);
            *(float2*)&gh[(lr + 8 + grp) * 8 + 2 * tq] =
                make_float2(acc0[2] + acc1[2], acc0[3] + acc1[3]);
        }
        __syncthreads();

        const int nxt = cur ^ 1;
        {
            float r = sigm_f(girA + gh[uA * 8 + bA] + bhrA);
            float z = sigm_f(gizA + gh[(80 + uA) * 8 + bA] + bhzA);
            float n = tanhf(ginA + r * (gh[(160 + uA) * 8 + bA] + bhnA));
            hA = (1.f - z) * n + z * hA;
            hbuf[nxt][bA * HST + gA] = hA;
            st_cluster_f32(prA[nxt], hA);
            if (layer == 0)
                yout[((size_t)t * 320 + dir * Hh + gA) * 256 + b0 + bA] = hA;
        }
        if (hasB) {
            float r = sigm_f(girB + gh[uB * 8 + bA] + bhrB);
            float z = sigm_f(gizB + gh[(80 + uB) * 8 + bA] + bhzB);
            float n = tanhf(ginB + r * (gh[(160 + uB) * 8 + bA] + bhnB));
            hB = (1.f - z) * n + z * hB;
            hbuf[nxt][bA * HST + gB] = hB;
            st_cluster_f32(prB[nxt], hB);
            if (layer == 0)
                yout[((size_t)t * 320 + dir * Hh + gB) * 256 + b0 + bA] = hB;
        }
        CLUSTER_ARRIVE();   // release this step's h stores (local + peer)
        cur = nxt;
    }
    CLUSTER_WAIT();   // drain final phase before exit

    if (layer == 1) {
        yout[((size_t)(dir * Bb) + b0 + bA) * Hh + gA] = hA;
        if (hasB) yout[((size_t)(dir * Bb) + b0 + bA) * Hh + gB] = hB;
    }
}

// ---------------------------------------------------------------------------
// K5: head
// ---------------------------------------------------------------------------
__global__ __launch_bounds__(128)
void head_kernel(const float* __restrict__ hfin,
                 const float* __restrict__ fc1w, const float* __restrict__ fc1b,
                 const float* __restrict__ fc2w, const float* __restrict__ fc2b,
                 float* __restrict__ out) {
    const int b = blockIdx.x;
    const int j = threadIdx.x;
    __shared__ float hv[320];
    __shared__ float red[4];

    for (int k = j; k < Hh; k += 128) {
        hv[k]      = hfin[(size_t)b * Hh + k];
        hv[Hh + k] = hfin[(size_t)Bb * Hh + (size_t)b * Hh + k];
    }
    __syncthreads();

    float acc = fc1b[j];
    const float* wr = fc1w + (size_t)j * 320;
#pragma unroll 8
    for (int k = 0; k < 320; k++) acc += wr[k] * hv[k];
    float v = fmaxf(acc, 0.f) * fc2w[j];

#pragma unroll
    for (int o = 16; o > 0; o >>= 1) v += __shfl_down_sync(0xffffffffu, v, o);
    if ((j & 31) == 0) red[j >> 5] = v;
    __syncthreads();
    if (j == 0) out[b] = red[0] + red[1] + red[2] + red[3] + fc2b[0];
}

// ---------------------------------------------------------------------------
// kernel_launch
// ---------------------------------------------------------------------------
extern "C" void kernel_launch(void* const* d_in, const int* in_sizes, int n_in,
                              void* d_out, int out_size) {
    const int*   x        = (const int*)  d_in[0];
    const float* emb      = (const float*)d_in[1];
    const float* Wih_l0f  = (const float*)d_in[2];
    const float* Whh_l0f  = (const float*)d_in[3];
    const float* bih_l0f  = (const float*)d_in[4];
    const float* bhh_l0f  = (const float*)d_in[5];
    const float* Wih_l0b  = (const float*)d_in[6];
    const float* Whh_l0b  = (const float*)d_in[7];
    const float* bih_l0b  = (const float*)d_in[8];
    const float* bhh_l0b  = (const float*)d_in[9];
    const float* Wih_l1f  = (const float*)d_in[10];
    const float* Whh_l1f  = (const float*)d_in[11];
    const float* bih_l1f  = (const float*)d_in[12];
    const float* bhh_l1f  = (const float*)d_in[13];
    const float* Wih_l1b  = (const float*)d_in[14];
    const float* Whh_l1b  = (const float*)d_in[15];
    const float* bih_l1b  = (const float*)d_in[16];
    const float* bhh_l1b  = (const float*)d_in[17];
    const float* fc1_w    = (const float*)d_in[18];
    const float* fc1_b    = (const float*)d_in[19];
    const float* fc2_w    = (const float*)d_in[20];
    const float* fc2_b    = (const float*)d_in[21];
    float* out = (float*)d_out;

    float *gi0, *gi1, *y0, *hfin;
    cudaGetSymbolAddress((void**)&gi0,  g_gi0);
    cudaGetSymbolAddress((void**)&gi1,  g_gi1);
    cudaGetSymbolAddress((void**)&y0,   g_y0);
    cudaGetSymbolAddress((void**)&hfin, g_hfin);

    {
        dim3 grid(Mrows / 128, G3 / 96, 2);
        gates_mma_kernel<128, true><<<grid, 256>>>(emb, x, Wih_l0f, Wih_l0b,
                                                   bih_l0f, bih_l0b, gi0);
    }

    scan_mma_kernel<<<dim3(64, 2), 512>>>(gi0, Whh_l0f, Whh_l0b,
                                          bhh_l0f, bhh_l0b, y0, 0);

    {
        dim3 grid(Mrows / 128, G3 / 96, 2);
        gates_mma_kernel<320, false><<<grid, 256>>>(y0, nullptr, Wih_l1f, Wih_l1b,
                                                    bih_l1f, bih_l1b, gi1);
    }

    scan_mma_kernel<<<dim3(64, 2), 512>>>(gi1, Whh_l1f, Whh_l1b,
                                          bhh_l1f, bhh_l1b, hfin, 1);

    head_kernel<<<Bb, 128>>>(hfin, fc1_w, fc1_b, fc2_w, fc2_b, out);
}

// round 6
// speedup vs baseline: 4.0188x; 1.0486x over previous
#include <cuda_runtime.h>
#include <math.h>
#include <stdint.h>

// ---------------------------------------------------------------------------
// TextGRUClassifier: 2-layer bidir GRU (B=256,T=512,E=128,H=160) + FC head
// R6: scan mma-loop de-bloated (pre-rounded tf32 h in smem, permuted-k float2
//     B-fragment loads) + per-step cluster sync via ping-pong mbarriers
//     (arrive.release.cluster on peer / try_wait.parity.acquire.cluster).
//     GEMMs + head unchanged from R5.
// ---------------------------------------------------------------------------

#define Tt 512
#define Bb 256
#define Hh 160
#define G3 480
#define Mrows (Tt*Bb)     // 131072

typedef unsigned long long u64;

// ---- scratch ----
static __device__ float g_gi0[(size_t)2 * Mrows * G3];   // [dir][t][n=480][b=256]
static __device__ float g_gi1[(size_t)2 * Mrows * G3];
static __device__ float g_y0[(size_t)Mrows * 320];       // [t][n=320][b=256]
static __device__ float g_hfin[2 * Bb * Hh];             // [dir][b][g]

// ---- helpers ----
__device__ __forceinline__ float sigm_f(float x) { return 1.f / (1.f + __expf(-x)); }

__device__ __forceinline__ uint32_t f2tf32(float x) {
    uint32_t r;
    asm("cvt.rna.tf32.f32 %0, %1;" : "=r"(r) : "f"(x));
    return r;
}
__device__ __forceinline__ void mma_tf32(float* d, const uint32_t* a, const uint32_t* b) {
    asm volatile(
        "mma.sync.aligned.m16n8k8.row.col.f32.tf32.tf32.f32 "
        "{%0,%1,%2,%3}, {%4,%5,%6,%7}, {%8,%9}, {%0,%1,%2,%3};"
        : "+f"(d[0]), "+f"(d[1]), "+f"(d[2]), "+f"(d[3])
        : "r"(a[0]), "r"(a[1]), "r"(a[2]), "r"(a[3]), "r"(b[0]), "r"(b[1]));
}
__device__ __forceinline__ uint32_t smem_u32(const void* p) {
    uint32_t a;
    asm("{ .reg .u64 t; cvta.to.shared.u64 t, %1; cvt.u32.u64 %0, t; }" : "=r"(a) : "l"(p));
    return a;
}
__device__ __forceinline__ uint32_t mapa_peer(uint32_t addr, uint32_t rank) {
    uint32_t r;
    asm("mapa.shared::cluster.u32 %0, %1, %2;" : "=r"(r) : "r"(addr), "r"(rank));
    return r;
}
__device__ __forceinline__ void st_cluster_u32(uint32_t addr, uint32_t v) {
    asm volatile("st.shared::cluster.u32 [%0], %1;" :: "r"(addr), "r"(v) : "memory");
}
__device__ __forceinline__ void mbar_init(uint32_t addr, uint32_t count) {
    asm volatile("mbarrier.init.shared.b64 [%0], %1;" :: "r"(addr), "r"(count) : "memory");
}
__device__ __forceinline__ void mbar_arrive_peer(uint32_t remote_addr) {
    asm volatile("mbarrier.arrive.release.cluster.shared::cluster.b64 _, [%0];"
                 :: "r"(remote_addr) : "memory");
}
__device__ __forceinline__ void mbar_wait_parity(uint32_t addr, uint32_t parity) {
    uint32_t done;
    asm volatile(
        "{\n\t.reg .pred p;\n\t"
        "mbarrier.try_wait.parity.acquire.cluster.shared::cta.b64 p, [%1], %2;\n\t"
        "selp.b32 %0, 1, 0, p;\n\t}"
        : "=r"(done) : "r"(addr), "r"(parity) : "memory");
    if (!done) {
        asm volatile(
            "{\n\t.reg .pred P1;\n\t"
            "WAIT_LOOP_%=:\n\t"
            "mbarrier.try_wait.parity.acquire.cluster.shared::cta.b64 P1, [%0], %1, 0x989680;\n\t"
            "@P1 bra.uni WAIT_DONE_%=;\n\t"
            "bra.uni WAIT_LOOP_%=;\n\t"
            "WAIT_DONE_%=:\n\t}"
            :: "r"(addr), "r"(parity) : "memory");
    }
}
#define CLUSTER_SYNC() do { \
    asm volatile("barrier.cluster.arrive.aligned;" ::: "memory"); \
    asm volatile("barrier.cluster.wait.aligned;" ::: "memory"); \
} while (0)

// ---------------------------------------------------------------------------
// K1/K3: gates GEMM on tf32 tensor cores (unchanged from R5).
//   out layout: [dir][t][n=480][b=256].
// ---------------------------------------------------------------------------
#define ALD 36
#define MLD 136

template <int KDIM, bool GATHER>
__global__ __launch_bounds__(256, 2)
void gates_mma_kernel(const float* __restrict__ A, const int* __restrict__ xids,
                      const float* __restrict__ Wf, const float* __restrict__ Wb,
                      const float* __restrict__ bf, const float* __restrict__ bb,
                      float* __restrict__ out) {
    const int m0 = blockIdx.x * 128;
    const int n0 = blockIdx.y * 96;
    const int dir = blockIdx.z;
    const float* W = dir ? Wb : Wf;
    const float* bias = dir ? bb : bf;
    float* outp = out + (size_t)dir * Mrows * G3;

    __shared__ float As[128 * ALD];
    __shared__ float Bs[96 * ALD];
    __shared__ int rid[128];

    const int tid = threadIdx.x;
    if (GATHER) {
        if (tid < 128) {
            int m = m0 + tid;
            rid[tid] = xids[(m & 255) * Tt + (m >> 8)];
        }
        __syncthreads();
    }

    const int lane = tid & 31, wid = tid >> 5;
    const int grp = lane >> 2, tq = lane & 3;
    const int m_off = (wid >> 1) * 32;
    const int n_off = (wid & 1) * 48;

    float acc[2][6][4];
#pragma unroll
    for (int i = 0; i < 2; i++)
#pragma unroll
        for (int j = 0; j < 6; j++)
#pragma unroll
            for (int c = 0; c < 4; c++) acc[i][j][c] = 0.f;

    const int rA = tid >> 3;
    const int cA = tid & 7;
    const float* arow[4];
    if (GATHER) {
#pragma unroll
        for (int u = 0; u < 4; u++) arow[u] = A + (size_t)rid[rA + u * 32] * KDIM;
    }
    const float* Abase = GATHER ? nullptr
                        : A + ((size_t)(m0 >> 8) * KDIM) * 256 + (m0 & 255);

    const float* brow[3];
#pragma unroll
    for (int u = 0; u < 3; u++) brow[u] = W + (size_t)(n0 + rA + u * 32) * KDIM;

    const int KT = KDIM / 32;
    float4 aR[4], bR[3];

    if (GATHER) {
#pragma unroll
        for (int u = 0; u < 4; u++) aR[u] = *(const float4*)(arow[u] + cA * 4);
    } else {
#pragma unroll
        for (int u = 0; u < 4; u++) {
            int idx = u * 256 + tid;
            int k = idx >> 5, m4 = (idx & 31) * 4;
            aR[u] = *(const float4*)(Abase + (size_t)k * 256 + m4);
        }
    }
#pragma unroll
    for (int u = 0; u < 3; u++) bR[u] = *(const float4*)(brow[u] + cA * 4);

    for (int kt = 0; kt < KT; kt++) {
        __syncthreads();
        if (GATHER) {
#pragma unroll
            for (int u = 0; u < 4; u++) {
                float4 v = aR[u];
                float4 w4 = make_float4(__uint_as_float(f2tf32(v.x)), __uint_as_float(f2tf32(v.y)),
                                        __uint_as_float(f2tf32(v.z)), __uint_as_float(f2tf32(v.w)));
                *(float4*)&As[(rA + u * 32) * ALD + cA * 4] = w4;
            }
        } else {
#pragma unroll
            for (int u = 0; u < 4; u++) {
                int idx = u * 256 + tid;
                int k = idx >> 5, m4 = (idx & 31) * 4;
                float4 v = aR[u];
                float4 w4 = make_float4(__uint_as_float(f2tf32(v.x)), __uint_as_float(f2tf32(v.y)),
                                        __uint_as_float(f2tf32(v.z)), __uint_as_float(f2tf32(v.w)));
                *(float4*)&As[k * MLD + m4] = w4;
            }
        }
#pragma unroll
        for (int u = 0; u < 3; u++) {
            float4 v = bR[u];
            float4 w4 = make_float4(__uint_as_float(f2tf32(v.x)), __uint_as_float(f2tf32(v.y)),
                                    __uint_as_float(f2tf32(v.z)), __uint_as_float(f2tf32(v.w)));
            *(float4*)&Bs[(rA + u * 32) * ALD + cA * 4] = w4;
        }
        __syncthreads();

        if (kt + 1 < KT) {
            int ko = (kt + 1) * 32;
            if (GATHER) {
#pragma unroll
                for (int u = 0; u < 4; u++) aR[u] = *(const float4*)(arow[u] + ko + cA * 4);
            } else {
#pragma unroll
                for (int u = 0; u < 4; u++) {
                    int idx = u * 256 + tid;
                    int k = idx >> 5, m4 = (idx & 31) * 4;
                    aR[u] = *(const float4*)(Abase + (size_t)(ko + k) * 256 + m4);
                }
            }
#pragma unroll
            for (int u = 0; u < 3; u++) bR[u] = *(const float4*)(brow[u] + ko + cA * 4);
        }

#pragma unroll
        for (int kc = 0; kc < 4; kc++) {
            const int kk0 = kc * 8;
            uint32_t af[2][4];
            if (GATHER) {
#pragma unroll
                for (int i = 0; i < 2; i++) {
                    int rm = m_off + i * 16;
                    af[i][0] = __float_as_uint(As[(rm + grp) * ALD + kk0 + tq]);
                    af[i][1] = __float_as_uint(As[(rm + 8 + grp) * ALD + kk0 + tq]);
                    af[i][2] = __float_as_uint(As[(rm + grp) * ALD + kk0 + tq + 4]);
                    af[i][3] = __float_as_uint(As[(rm + 8 + grp) * ALD + kk0 + tq + 4]);
                }
            } else {
#pragma unroll
                for (int i = 0; i < 2; i++) {
                    int rm = m_off + i * 16;
                    af[i][0] = __float_as_uint(As[(kk0 + tq) * MLD + rm + grp]);
                    af[i][1] = __float_as_uint(As[(kk0 + tq) * MLD + rm + 8 + grp]);
                    af[i][2] = __float_as_uint(As[(kk0 + tq + 4) * MLD + rm + grp]);
                    af[i][3] = __float_as_uint(As[(kk0 + tq + 4) * MLD + rm + 8 + grp]);
                }
            }
            uint32_t bfr[6][2];
#pragma unroll
            for (int j = 0; j < 6; j++) {
                int nb = n_off + j * 8;
                bfr[j][0] = __float_as_uint(Bs[(nb + grp) * ALD + kk0 + tq]);
                bfr[j][1] = __float_as_uint(Bs[(nb + grp) * ALD + kk0 + tq + 4]);
            }
#pragma unroll
            for (int i = 0; i < 2; i++)
#pragma unroll
                for (int j = 0; j < 6; j++) mma_tf32(acc[i][j], af[i], bfr[j]);
        }
    }

    {
        const int t_t = m0 >> 8;
        const int bb = m0 & 255;
        float* ob = outp + (size_t)t_t * G3 * 256 + bb;
#pragma unroll
        for (int j = 0; j < 6; j++) {
            int col = n0 + n_off + j * 8 + 2 * tq;
            float b0v = bias[col], b1v = bias[col + 1];
#pragma unroll
            for (int i = 0; i < 2; i++) {
                int ml = m_off + i * 16 + grp;
                ob[(size_t)col * 256 + ml]           = acc[i][j][0] + b0v;
                ob[(size_t)(col + 1) * 256 + ml]     = acc[i][j][1] + b1v;
                ob[(size_t)col * 256 + ml + 8]       = acc[i][j][2] + b0v;
                ob[(size_t)(col + 1) * 256 + ml + 8] = acc[i][j][3] + b1v;
            }
        }
    }
}

// ---------------------------------------------------------------------------
// K2/K4: GRU scan on tensor cores, 2-CTA cluster (as R5) with:
//  - hbuf holds PRE-ROUNDED tf32 h values in a k-permuted layout so a B
//    fragment pair (k=tq, k=tq+4) is one contiguous float2 (no cvt, 1 LDS.64);
//  - per-step cluster handshake via ping-pong mbarriers instead of
//    barrier.cluster.
//  k-permutation within each 8-group: j -> ((j&3)<<1) | (j>>2).
// ---------------------------------------------------------------------------
#define HST 168                  // h row stride (floats); 168 % 32 == 8
#define HBUFN (8 * HST)

__global__ __launch_bounds__(512) __cluster_dims__(2, 1, 1)
void scan_mma_kernel(const float* __restrict__ gi,
                     const float* __restrict__ whhF, const float* __restrict__ whhB,
                     const float* __restrict__ bhf, const float* __restrict__ bhb,
                     float* __restrict__ yout, int layer) {
    __shared__ __align__(16) float hbuf[2][HBUFN];   // [buf][b][perm(k)] (tf32 bits)
    __shared__ float gh[240 * 8];                    // [lr][b]
    __shared__ __align__(8) unsigned long long mbar[2];

    const int dir = blockIdx.y;
    const int rank = blockIdx.x & 1;
    const int b0 = (blockIdx.x >> 1) * 8;
    const int tid = threadIdx.x;
    const int wid = tid >> 5, lane = tid & 31;
    const int grp = lane >> 2, tq = lane & 3;

    const uint32_t mbar0 = smem_u32(&mbar[0]);
    const uint32_t mbar1 = smem_u32(&mbar[1]);
    const uint32_t pbar0 = mapa_peer(mbar0, rank ^ 1);
    const uint32_t pbar1 = mapa_peer(mbar1, rank ^ 1);
    if (tid == 0) {
        mbar_init(mbar0, 1);
        mbar_init(mbar1, 1);
    }

    // ---- preload Whh A-fragments into registers (tf32-rounded) ----
    uint32_t wreg[80];
    const bool is_mma = (wid < 15);
    if (is_mma) {
        const int gate = wid / 5, mseg = wid % 5;
        const int gr0 = gate * Hh + rank * 80 + mseg * 16 + grp;   // global Whh row
        const float* W = dir ? whhB : whhF;
#pragma unroll
        for (int kt = 0; kt < 20; kt++) {
            wreg[kt * 4 + 0] = f2tf32(W[(size_t)gr0 * Hh + kt * 8 + tq]);
            wreg[kt * 4 + 1] = f2tf32(W[(size_t)(gr0 + 8) * Hh + kt * 8 + tq]);
            wreg[kt * 4 + 2] = f2tf32(W[(size_t)gr0 * Hh + kt * 8 + tq + 4]);
            wreg[kt * 4 + 3] = f2tf32(W[(size_t)(gr0 + 8) * Hh + kt * 8 + tq + 4]);
        }
    }

    // ---- combine-item setup ----
    const int uA = tid >> 3, bA = tid & 7;
    const int gA = rank * 80 + uA;
    const int pgA = (gA & ~7) | (((gA & 3) << 1) | ((gA >> 2) & 1));
    const float* bh = dir ? bhb : bhf;
    const float bhrA = bh[gA], bhzA = bh[Hh + gA], bhnA = bh[2 * Hh + gA];
    const float* gib = gi + (size_t)dir * Mrows * G3;
    const float* giA = gib + (size_t)gA * 256 + b0 + bA;
    uint32_t prA[2];
    prA[0] = mapa_peer(smem_u32(&hbuf[0][bA * HST + pgA]), rank ^ 1);
    prA[1] = mapa_peer(smem_u32(&hbuf[1][bA * HST + pgA]), rank ^ 1);

    const bool hasB = (tid < 128);
    const int uB = 64 + (tid >> 3), gB = rank * 80 + uB;
    const int pgB = (gB & ~7) | (((gB & 3) << 1) | ((gB >> 2) & 1));
    float bhrB = 0.f, bhzB = 0.f, bhnB = 0.f;
    const float* giB = giA;
    uint32_t prB[2] = {0u, 0u};
    if (hasB) {
        bhrB = bh[gB]; bhzB = bh[Hh + gB]; bhnB = bh[2 * Hh + gB];
        giB = gib + (size_t)gB * 256 + b0 + bA;
        prB[0] = mapa_peer(smem_u32(&hbuf[0][bA * HST + pgB]), rank ^ 1);
        prB[1] = mapa_peer(smem_u32(&hbuf[1][bA * HST + pgB]), rank ^ 1);
    }

    for (int i = tid; i < 2 * HBUFN; i += 512) (&hbuf[0][0])[i] = 0.f;
    __syncthreads();
    CLUSTER_SYNC();   // hbuf zero-init + mbar init visible cluster-wide

    float hA = 0.f, hB = 0.f;
    int cur = 0;

    for (int s = 0; s < Tt; s++) {
        const int t = dir ? (Tt - 1 - s) : s;
        const size_t toff = (size_t)t * G3 * 256;

        // issue gi loads before blocking on the handshake (hides DRAM)
        float girA = giA[toff], gizA = giA[toff + (size_t)Hh * 256],
              ginA = giA[toff + (size_t)2 * Hh * 256];
        float girB = 0.f, gizB = 0.f, ginB = 0.f;
        if (hasB) {
            girB = giB[toff]; gizB = giB[toff + (size_t)Hh * 256];
            ginB = giB[toff + (size_t)2 * Hh * 256];
        }

        // wait for peer's h stores into hbuf[cur] (skip s=0: zero-init, synced)
        if (s > 0) {
            mbar_wait_parity((s & 1) ? mbar1 : mbar0, ((s - 1) >> 1) & 1);
        }

        if (is_mma) {
            const float* hc = hbuf[cur];
            float acc0[4] = {0.f, 0.f, 0.f, 0.f};
            float acc1[4] = {0.f, 0.f, 0.f, 0.f};
#pragma unroll
            for (int kt = 0; kt < 20; kt += 2) {
                float2 v0 = *(const float2*)&hc[grp * HST + kt * 8 + tq * 2];
                mma_tf32(acc0, &wreg[kt * 4], (const uint32_t*)&v0);
                float2 v1 = *(const float2*)&hc[grp * HST + (kt + 1) * 8 + tq * 2];
                mma_tf32(acc1, &wreg[(kt + 1) * 4], (const uint32_t*)&v1);
            }
            const int lr = wid * 16;
            *(float2*)&gh[(lr + grp) * 8 + 2 * tq] =
                make_float2(acc0[0] + acc1[0], acc0[1] + acc1[1]);
            *(float2*)&gh[(lr + 8 + grp) * 8 + 2 * tq] =
                make_float2(acc0[2] + acc1[2], acc0[3] + acc1[3]);
        }
        __syncthreads();

        const int nxt = cur ^ 1;
        {
            float r = sigm_f(girA + gh[uA * 8 + bA] + bhrA);
            float z = sigm_f(gizA + gh[(80 + uA) * 8 + bA] + bhzA);
            float n = tanhf(ginA + r * (gh[(160 + uA) * 8 + bA] + bhnA));
            hA = (1.f - z) * n + z * hA;
            uint32_t htf = f2tf32(hA);
            *(uint32_t*)&hbuf[nxt][bA * HST + pgA] = htf;
            st_cluster_u32(prA[nxt], htf);
            if (layer == 0)
                yout[((size_t)t * 320 + dir * Hh + gA) * 256 + b0 + bA] = hA;
        }
        if (hasB) {
            float r = sigm_f(girB + gh[uB * 8 + bA] + bhrB);
            float z = sigm_f(gizB + gh[(80 + uB) * 8 + bA] + bhzB);
            float n = tanhf(ginB + r * (gh[(160 + uB) * 8 + bA] + bhnB));
            hB = (1.f - z) * n + z * hB;
            uint32_t htf = f2tf32(hB);
            *(uint32_t*)&hbuf[nxt][bA * HST + pgB] = htf;
            st_cluster_u32(prB[nxt], htf);
            if (layer == 0)
                yout[((size_t)t * 320 + dir * Hh + gB) * 256 + b0 + bA] = hB;
        }
        __syncthreads();   // all peer stores issued; orders them before the release
        if (tid == 0) {
            // signal peer: its hbuf[nxt] is fully written by us
            mbar_arrive_peer((nxt & 1) ? pbar1 : pbar0);
        }
        cur = nxt;
    }

    if (layer == 1) {
        yout[((size_t)(dir * Bb) + b0 + bA) * Hh + gA] = hA;
        if (hasB) yout[((size_t)(dir * Bb) + b0 + bA) * Hh + gB] = hB;
    }
    CLUSTER_SYNC();   // no CTA exits while peer stores into its smem may be in flight
}

// ---------------------------------------------------------------------------
// K5: head
// ---------------------------------------------------------------------------
__global__ __launch_bounds__(128)
void head_kernel(const float* __restrict__ hfin,
                 const float* __restrict__ fc1w, const float* __restrict__ fc1b,
                 const float* __restrict__ fc2w, const float* __restrict__ fc2b,
                 float* __restrict__ out) {
    const int b = blockIdx.x;
    const int j = threadIdx.x;
    __shared__ float hv[320];
    __shared__ float red[4];

    for (int k = j; k < Hh; k += 128) {
        hv[k]      = hfin[(size_t)b * Hh + k];
        hv[Hh + k] = hfin[(size_t)Bb * Hh + (size_t)b * Hh + k];
    }
    __syncthreads();

    float acc = fc1b[j];
    const float* wr = fc1w + (size_t)j * 320;
#pragma unroll 8
    for (int k = 0; k < 320; k++) acc += wr[k] * hv[k];
    float v = fmaxf(acc, 0.f) * fc2w[j];

#pragma unroll
    for (int o = 16; o > 0; o >>= 1) v += __shfl_down_sync(0xffffffffu, v, o);
    if ((j & 31) == 0) red[j >> 5] = v;
    __syncthreads();
    if (j == 0) out[b] = red[0] + red[1] + red[2] + red[3] + fc2b[0];
}

// ---------------------------------------------------------------------------
// kernel_launch
// ---------------------------------------------------------------------------
extern "C" void kernel_launch(void* const* d_in, const int* in_sizes, int n_in,
                              void* d_out, int out_size) {
    const int*   x        = (const int*)  d_in[0];
    const float* emb      = (const float*)d_in[1];
    const float* Wih_l0f  = (const float*)d_in[2];
    const float* Whh_l0f  = (const float*)d_in[3];
    const float* bih_l0f  = (const float*)d_in[4];
    const float* bhh_l0f  = (const float*)d_in[5];
    const float* Wih_l0b  = (const float*)d_in[6];
    const float* Whh_l0b  = (const float*)d_in[7];
    const float* bih_l0b  = (const float*)d_in[8];
    const float* bhh_l0b  = (const float*)d_in[9];
    const float* Wih_l1f  = (const float*)d_in[10];
    const float* Whh_l1f  = (const float*)d_in[11];
    const float* bih_l1f  = (const float*)d_in[12];
    const float* bhh_l1f  = (const float*)d_in[13];
    const float* Wih_l1b  = (const float*)d_in[14];
    const float* Whh_l1b  = (const float*)d_in[15];
    const float* bih_l1b  = (const float*)d_in[16];
    const float* bhh_l1b  = (const float*)d_in[17];
    const float* fc1_w    = (const float*)d_in[18];
    const float* fc1_b    = (const float*)d_in[19];
    const float* fc2_w    = (const float*)d_in[20];
    const float* fc2_b    = (const float*)d_in[21];
    float* out = (float*)d_out;

    float *gi0, *gi1, *y0, *hfin;
    cudaGetSymbolAddress((void**)&gi0,  g_gi0);
    cudaGetSymbolAddress((void**)&gi1,  g_gi1);
    cudaGetSymbolAddress((void**)&y0,   g_y0);
    cudaGetSymbolAddress((void**)&hfin, g_hfin);

    {
        dim3 grid(Mrows / 128, G3 / 96, 2);
        gates_mma_kernel<128, true><<<grid, 256>>>(emb, x, Wih_l0f, Wih_l0b,
                                                   bih_l0f, bih_l0b, gi0);
    }

    scan_mma_kernel<<<dim3(64, 2), 512>>>(gi0, Whh_l0f, Whh_l0b,
                                          bhh_l0f, bhh_l0b, y0, 0);

    {
        dim3 grid(Mrows / 128, G3 / 96, 2);
        gates_mma_kernel<320, false><<<grid, 256>>>(y0, nullptr, Wih_l1f, Wih_l1b,
                                                    bih_l1f, bih_l1b, gi1);
    }

    scan_mma_kernel<<<dim3(64, 2), 512>>>(gi1, Whh_l1f, Whh_l1b,
                                          bhh_l1f, bhh_l1b, hfin, 1);

    head_kernel<<<Bb, 128>>>(hfin, fc1_w, fc1_b, fc2_w, fc2_b, out);
}

// round 7
// speedup vs baseline: 4.7567x; 1.1836x over previous
#include <cuda_runtime.h>
#include <math.h>
#include <stdint.h>

// ---------------------------------------------------------------------------
// TextGRUClassifier: 2-layer bidir GRU (B=256,T=512,E=128,H=160) + FC head
// R7: scan critical-path surgery:
//  - k-split mma: own-half h mma runs BEFORE the peer mbar wait (hides DSMEM
//    handshake), peer-half after -> post-wait chain only 5 mma deep
//  - tanh.approx.f32 for all three gates (sigmoid via tanh identity)
//  - gi staged one step ahead via cp.async double buffer in smem
// GEMMs + head unchanged from R6.
// ---------------------------------------------------------------------------

#define Tt 512
#define Bb 256
#define Hh 160
#define G3 480
#define Mrows (Tt*Bb)     // 131072

typedef unsigned long long u64;

// ---- scratch ----
static __device__ float g_gi0[(size_t)2 * Mrows * G3];   // [dir][t][n=480][b=256]
static __device__ float g_gi1[(size_t)2 * Mrows * G3];
static __device__ float g_y0[(size_t)Mrows * 320];       // [t][n=320][b=256]
static __device__ float g_hfin[2 * Bb * Hh];             // [dir][b][g]

// ---- helpers ----
__device__ __forceinline__ float tanh_ap(float x) {
    float r;
    asm("tanh.approx.f32 %0, %1;" : "=f"(r) : "f"(x));
    return r;
}
__device__ __forceinline__ uint32_t f2tf32(float x) {
    uint32_t r;
    asm("cvt.rna.tf32.f32 %0, %1;" : "=r"(r) : "f"(x));
    return r;
}
__device__ __forceinline__ void mma_tf32(float* d, const uint32_t* a, const uint32_t* b) {
    asm volatile(
        "mma.sync.aligned.m16n8k8.row.col.f32.tf32.tf32.f32 "
        "{%0,%1,%2,%3}, {%4,%5,%6,%7}, {%8,%9}, {%0,%1,%2,%3};"
        : "+f"(d[0]), "+f"(d[1]), "+f"(d[2]), "+f"(d[3])
        : "r"(a[0]), "r"(a[1]), "r"(a[2]), "r"(a[3]), "r"(b[0]), "r"(b[1]));
}
__device__ __forceinline__ uint32_t smem_u32(const void* p) {
    uint32_t a;
    asm("{ .reg .u64 t; cvta.to.shared.u64 t, %1; cvt.u32.u64 %0, t; }" : "=r"(a) : "l"(p));
    return a;
}
__device__ __forceinline__ uint32_t mapa_peer(uint32_t addr, uint32_t rank) {
    uint32_t r;
    asm("mapa.shared::cluster.u32 %0, %1, %2;" : "=r"(r) : "r"(addr), "r"(rank));
    return r;
}
__device__ __forceinline__ void st_cluster_u32(uint32_t addr, uint32_t v) {
    asm volatile("st.shared::cluster.u32 [%0], %1;" :: "r"(addr), "r"(v) : "memory");
}
__device__ __forceinline__ void cp_async4(uint32_t dst, const void* src) {
    asm volatile("cp.async.ca.shared.global [%0], [%1], 4;" :: "r"(dst), "l"(src) : "memory");
}
__device__ __forceinline__ void cp_commit() {
    asm volatile("cp.async.commit_group;" ::: "memory");
}
__device__ __forceinline__ void cp_wait1() {
    asm volatile("cp.async.wait_group 1;" ::: "memory");
}
__device__ __forceinline__ void mbar_init(uint32_t addr, uint32_t count) {
    asm volatile("mbarrier.init.shared.b64 [%0], %1;" :: "r"(addr), "r"(count) : "memory");
}
__device__ __forceinline__ void mbar_arrive_peer(uint32_t remote_addr) {
    asm volatile("mbarrier.arrive.release.cluster.shared::cluster.b64 _, [%0];"
                 :: "r"(remote_addr) : "memory");
}
__device__ __forceinline__ void mbar_wait_parity(uint32_t addr, uint32_t parity) {
    uint32_t done;
    asm volatile(
        "{\n\t.reg .pred p;\n\t"
        "mbarrier.try_wait.parity.acquire.cluster.shared::cta.b64 p, [%1], %2;\n\t"
        "selp.b32 %0, 1, 0, p;\n\t}"
        : "=r"(done) : "r"(addr), "r"(parity) : "memory");
    if (!done) {
        asm volatile(
            "{\n\t.reg .pred P1;\n\t"
            "WAIT_LOOP_%=:\n\t"
            "mbarrier.try_wait.parity.acquire.cluster.shared::cta.b64 P1, [%0], %1, 0x989680;\n\t"
            "@P1 bra.uni WAIT_DONE_%=;\n\t"
            "bra.uni WAIT_LOOP_%=;\n\t"
            "WAIT_DONE_%=:\n\t}"
            :: "r"(addr), "r"(parity) : "memory");
    }
}
#define CLUSTER_SYNC() do { \
    asm volatile("barrier.cluster.arrive.aligned;" ::: "memory"); \
    asm volatile("barrier.cluster.wait.aligned;" ::: "memory"); \
} while (0)

// ---------------------------------------------------------------------------
// K1/K3: gates GEMM on tf32 tensor cores (unchanged from R6).
// ---------------------------------------------------------------------------
#define ALD 36
#define MLD 136

template <int KDIM, bool GATHER>
__global__ __launch_bounds__(256, 2)
void gates_mma_kernel(const float* __restrict__ A, const int* __restrict__ xids,
                      const float* __restrict__ Wf, const float* __restrict__ Wb,
                      const float* __restrict__ bf, const float* __restrict__ bb,
                      float* __restrict__ out) {
    const int m0 = blockIdx.x * 128;
    const int n0 = blockIdx.y * 96;
    const int dir = blockIdx.z;
    const float* W = dir ? Wb : Wf;
    const float* bias = dir ? bb : bf;
    float* outp = out + (size_t)dir * Mrows * G3;

    __shared__ float As[128 * ALD];
    __shared__ float Bs[96 * ALD];
    __shared__ int rid[128];

    const int tid = threadIdx.x;
    if (GATHER) {
        if (tid < 128) {
            int m = m0 + tid;
            rid[tid] = xids[(m & 255) * Tt + (m >> 8)];
        }
        __syncthreads();
    }

    const int lane = tid & 31, wid = tid >> 5;
    const int grp = lane >> 2, tq = lane & 3;
    const int m_off = (wid >> 1) * 32;
    const int n_off = (wid & 1) * 48;

    float acc[2][6][4];
#pragma unroll
    for (int i = 0; i < 2; i++)
#pragma unroll
        for (int j = 0; j < 6; j++)
#pragma unroll
            for (int c = 0; c < 4; c++) acc[i][j][c] = 0.f;

    const int rA = tid >> 3;
    const int cA = tid & 7;
    const float* arow[4];
    if (GATHER) {
#pragma unroll
        for (int u = 0; u < 4; u++) arow[u] = A + (size_t)rid[rA + u * 32] * KDIM;
    }
    const float* Abase = GATHER ? nullptr
                        : A + ((size_t)(m0 >> 8) * KDIM) * 256 + (m0 & 255);

    const float* brow[3];
#pragma unroll
    for (int u = 0; u < 3; u++) brow[u] = W + (size_t)(n0 + rA + u * 32) * KDIM;

    const int KT = KDIM / 32;
    float4 aR[4], bR[3];

    if (GATHER) {
#pragma unroll
        for (int u = 0; u < 4; u++) aR[u] = *(const float4*)(arow[u] + cA * 4);
    } else {
#pragma unroll
        for (int u = 0; u < 4; u++) {
            int idx = u * 256 + tid;
            int k = idx >> 5, m4 = (idx & 31) * 4;
            aR[u] = *(const float4*)(Abase + (size_t)k * 256 + m4);
        }
    }
#pragma unroll
    for (int u = 0; u < 3; u++) bR[u] = *(const float4*)(brow[u] + cA * 4);

    for (int kt = 0; kt < KT; kt++) {
        __syncthreads();
        if (GATHER) {
#pragma unroll
            for (int u = 0; u < 4; u++) {
                float4 v = aR[u];
                float4 w4 = make_float4(__uint_as_float(f2tf32(v.x)), __uint_as_float(f2tf32(v.y)),
                                        __uint_as_float(f2tf32(v.z)), __uint_as_float(f2tf32(v.w)));
                *(float4*)&As[(rA + u * 32) * ALD + cA * 4] = w4;
            }
        } else {
#pragma unroll
            for (int u = 0; u < 4; u++) {
                int idx = u * 256 + tid;
                int k = idx >> 5, m4 = (idx & 31) * 4;
                float4 v = aR[u];
                float4 w4 = make_float4(__uint_as_float(f2tf32(v.x)), __uint_as_float(f2tf32(v.y)),
                                        __uint_as_float(f2tf32(v.z)), __uint_as_float(f2tf32(v.w)));
                *(float4*)&As[k * MLD + m4] = w4;
            }
        }
#pragma unroll
        for (int u = 0; u < 3; u++) {
            float4 v = bR[u];
            float4 w4 = make_float4(__uint_as_float(f2tf32(v.x)), __uint_as_float(f2tf32(v.y)),
                                    __uint_as_float(f2tf32(v.z)), __uint_as_float(f2tf32(v.w)));
            *(float4*)&Bs[(rA + u * 32) * ALD + cA * 4] = w4;
        }
        __syncthreads();

        if (kt + 1 < KT) {
            int ko = (kt + 1) * 32;
            if (GATHER) {
#pragma unroll
                for (int u = 0; u < 4; u++) aR[u] = *(const float4*)(arow[u] + ko + cA * 4);
            } else {
#pragma unroll
                for (int u = 0; u < 4; u++) {
                    int idx = u * 256 + tid;
                    int k = idx >> 5, m4 = (idx & 31) * 4;
                    aR[u] = *(const float4*)(Abase + (size_t)(ko + k) * 256 + m4);
                }
            }
#pragma unroll
            for (int u = 0; u < 3; u++) bR[u] = *(const float4*)(brow[u] + ko + cA * 4);
        }

#pragma unroll
        for (int kc = 0; kc < 4; kc++) {
            const int kk0 = kc * 8;
            uint32_t af[2][4];
            if (GATHER) {
#pragma unroll
                for (int i = 0; i < 2; i++) {
                    int rm = m_off + i * 16;
                    af[i][0] = __float_as_uint(As[(rm + grp) * ALD + kk0 + tq]);
                    af[i][1] = __float_as_uint(As[(rm + 8 + grp) * ALD + kk0 + tq]);
                    af[i][2] = __float_as_uint(As[(rm + grp) * ALD + kk0 + tq + 4]);
                    af[i][3] = __float_as_uint(As[(rm + 8 + grp) * ALD + kk0 + tq + 4]);
                }
            } else {
#pragma unroll
                for (int i = 0; i < 2; i++) {
                    int rm = m_off + i * 16;
                    af[i][0] = __float_as_uint(As[(kk0 + tq) * MLD + rm + grp]);
                    af[i][1] = __float_as_uint(As[(kk0 + tq) * MLD + rm + 8 + grp]);
                    af[i][2] = __float_as_uint(As[(kk0 + tq + 4) * MLD + rm + grp]);
                    af[i][3] = __float_as_uint(As[(kk0 + tq + 4) * MLD + rm + 8 + grp]);
                }
            }
            uint32_t bfr[6][2];
#pragma unroll
            for (int j = 0; j < 6; j++) {
                int nb = n_off + j * 8;
                bfr[j][0] = __float_as_uint(Bs[(nb + grp) * ALD + kk0 + tq]);
                bfr[j][1] = __float_as_uint(Bs[(nb + grp) * ALD + kk0 + tq + 4]);
            }
#pragma unroll
            for (int i = 0; i < 2; i++)
#pragma unroll
                for (int j = 0; j < 6; j++) mma_tf32(acc[i][j], af[i], bfr[j]);
        }
    }

    {
        const int t_t = m0 >> 8;
        const int bb = m0 & 255;
        float* ob = outp + (size_t)t_t * G3 * 256 + bb;
#pragma unroll
        for (int j = 0; j < 6; j++) {
            int col = n0 + n_off + j * 8 + 2 * tq;
            float b0v = bias[col], b1v = bias[col + 1];
#pragma unroll
            for (int i = 0; i < 2; i++) {
                int ml = m_off + i * 16 + grp;
                ob[(size_t)col * 256 + ml]           = acc[i][j][0] + b0v;
                ob[(size_t)(col + 1) * 256 + ml]     = acc[i][j][1] + b1v;
                ob[(size_t)col * 256 + ml + 8]       = acc[i][j][2] + b0v;
                ob[(size_t)(col + 1) * 256 + ml + 8] = acc[i][j][3] + b1v;
            }
        }
    }
}

// ---------------------------------------------------------------------------
// K2/K4: GRU scan on tensor cores, 2-CTA cluster.
//   wreg layout: [0..39] = own-rank k half (kt = rank*10 + j), [40..79] = peer
//   half. Phase L (pre-wait) consumes own half; phase R (post-wait) peer half.
//   gi staged one step ahead via cp.async double buffer.
// ---------------------------------------------------------------------------
#define HST 168                  // h row stride (floats); 168 % 32 == 8
#define HBUFN (8 * HST)
#define GIN 1920                 // floats per gi stage buffer (3*512 + 3*128)

__global__ __launch_bounds__(512) __cluster_dims__(2, 1, 1)
void scan_mma_kernel(const float* __restrict__ gi,
                     const float* __restrict__ whhF, const float* __restrict__ whhB,
                     const float* __restrict__ bhf, const float* __restrict__ bhb,
                     float* __restrict__ yout, int layer) {
    __shared__ __align__(16) float hbuf[2][HBUFN];   // [buf][b][perm(k)] (tf32 bits)
    __shared__ float gh[240 * 8];                    // [lr][b]
    __shared__ __align__(16) float gis[2][GIN];      // staged gi values
    __shared__ __align__(8) unsigned long long mbar[2];

    const int dir = blockIdx.y;
    const int rank = blockIdx.x & 1;
    const int b0 = (blockIdx.x >> 1) * 8;
    const int tid = threadIdx.x;
    const int wid = tid >> 5, lane = tid & 31;
    const int grp = lane >> 2, tq = lane & 3;

    const uint32_t mbar0 = smem_u32(&mbar[0]);
    const uint32_t mbar1 = smem_u32(&mbar[1]);
    const uint32_t pbar0 = mapa_peer(mbar0, rank ^ 1);
    const uint32_t pbar1 = mapa_peer(mbar1, rank ^ 1);
    if (tid == 0) {
        mbar_init(mbar0, 1);
        mbar_init(mbar1, 1);
    }

    // ---- preload Whh A-fragments: [0..39] own-rank k half, [40..79] peer half ----
    uint32_t wreg[80];
    const bool is_mma = (wid < 15);
    const int ktL = rank * 10;          // own-half kt base (k = own units)
    const int ktR = (rank ^ 1) * 10;    // peer-half kt base
    if (is_mma) {
        const int gate = wid / 5, mseg = wid % 5;
        const int gr0 = gate * Hh + rank * 80 + mseg * 16 + grp;
        const float* W = dir ? whhB : whhF;
#pragma unroll
        for (int j = 0; j < 10; j++) {
            int kt = ktL + j;
            wreg[j * 4 + 0] = f2tf32(W[(size_t)gr0 * Hh + kt * 8 + tq]);
            wreg[j * 4 + 1] = f2tf32(W[(size_t)(gr0 + 8) * Hh + kt * 8 + tq]);
            wreg[j * 4 + 2] = f2tf32(W[(size_t)gr0 * Hh + kt * 8 + tq + 4]);
            wreg[j * 4 + 3] = f2tf32(W[(size_t)(gr0 + 8) * Hh + kt * 8 + tq + 4]);
        }
#pragma unroll
        for (int j = 0; j < 10; j++) {
            int kt = ktR + j;
            wreg[40 + j * 4 + 0] = f2tf32(W[(size_t)gr0 * Hh + kt * 8 + tq]);
            wreg[40 + j * 4 + 1] = f2tf32(W[(size_t)(gr0 + 8) * Hh + kt * 8 + tq]);
            wreg[40 + j * 4 + 2] = f2tf32(W[(size_t)gr0 * Hh + kt * 8 + tq + 4]);
            wreg[40 + j * 4 + 3] = f2tf32(W[(size_t)(gr0 + 8) * Hh + kt * 8 + tq + 4]);
        }
    }

    // ---- combine-item setup ----
    const int uA = tid >> 3, bA = tid & 7;
    const int gA = rank * 80 + uA;
    const int pgA = (gA & ~7) | (((gA & 3) << 1) | ((gA >> 2) & 1));
    const float* bh = dir ? bhb : bhf;
    const float bhrA = bh[gA], bhzA = bh[Hh + gA], bhnA = bh[2 * Hh + gA];
    const float* gib = gi + (size_t)dir * Mrows * G3;
    const float* giA = gib + (size_t)gA * 256 + b0 + bA;
    uint32_t prA[2];
    prA[0] = mapa_peer(smem_u32(&hbuf[0][bA * HST + pgA]), rank ^ 1);
    prA[1] = mapa_peer(smem_u32(&hbuf[1][bA * HST + pgA]), rank ^ 1);

    const bool hasB = (tid < 128);
    const int uB = 64 + (tid >> 3), gB = rank * 80 + uB;
    const int pgB = (gB & ~7) | (((gB & 3) << 1) | ((gB >> 2) & 1));
    float bhrB = 0.f, bhzB = 0.f, bhnB = 0.f;
    const float* giB = giA;
    uint32_t prB[2] = {0u, 0u};
    if (hasB) {
        bhrB = bh[gB]; bhzB = bh[Hh + gB]; bhnB = bh[2 * Hh + gB];
        giB = gib + (size_t)gB * 256 + b0 + bA;
        prB[0] = mapa_peer(smem_u32(&hbuf[0][bA * HST + pgB]), rank ^ 1);
        prB[1] = mapa_peer(smem_u32(&hbuf[1][bA * HST + pgB]), rank ^ 1);
    }

    // gi staging addresses (cp.async dst); slots A: 3x512 floats, B: 3x128
    const uint32_t gis_base = smem_u32(&gis[0][0]);
    const uint32_t gisA0 = gis_base + tid * 4;                // + slot*2048
    const uint32_t gisB0 = gis_base + 6144 + tid * 4;         // + slot*512

    for (int i = tid; i < 2 * HBUFN; i += 512) (&hbuf[0][0])[i] = 0.f;

    // prologue: stage gi for s=0 into gis[0]
    {
        const int t0 = dir ? (Tt - 1) : 0;
        const size_t toff = (size_t)t0 * G3 * 256;
        cp_async4(gisA0,        giA + toff);
        cp_async4(gisA0 + 2048, giA + toff + (size_t)Hh * 256);
        cp_async4(gisA0 + 4096, giA + toff + (size_t)2 * Hh * 256);
        if (hasB) {
            cp_async4(gisB0,        giB + toff);
            cp_async4(gisB0 + 512,  giB + toff + (size_t)Hh * 256);
            cp_async4(gisB0 + 1024, giB + toff + (size_t)2 * Hh * 256);
        }
        cp_commit();
    }

    __syncthreads();
    CLUSTER_SYNC();   // hbuf zero-init + mbar init visible cluster-wide

    float hA = 0.f, hB = 0.f;
    int cur = 0;

    for (int s = 0; s < Tt; s++) {
        // stage gi for s+1 into gis[cur^1]
        if (s + 1 < Tt) {
            const int tn = dir ? (Tt - 2 - s) : (s + 1);
            const size_t toff = (size_t)tn * G3 * 256;
            const uint32_t off = (cur ^ 1) * 7680;
            cp_async4(gisA0 + off,        giA + toff);
            cp_async4(gisA0 + off + 2048, giA + toff + (size_t)Hh * 256);
            cp_async4(gisA0 + off + 4096, giA + toff + (size_t)2 * Hh * 256);
            if (hasB) {
                cp_async4(gisB0 + off,        giB + toff);
                cp_async4(gisB0 + off + 512,  giB + toff + (size_t)Hh * 256);
                cp_async4(gisB0 + off + 1024, giB + toff + (size_t)2 * Hh * 256);
            }
        }
        cp_commit();

        if (is_mma) {
            float accA[4] = {0.f, 0.f, 0.f, 0.f};
            float accB4[4] = {0.f, 0.f, 0.f, 0.f};
            const float* hc = hbuf[cur];
            const int hbase = grp * HST;

            // ---- phase L: own-half k (local h, no peer dependency) ----
#pragma unroll
            for (int j = 0; j < 10; j += 2) {
                float2 v0 = *(const float2*)&hc[hbase + (ktL + j) * 8 + tq * 2];
                mma_tf32(accA, &wreg[j * 4], (const uint32_t*)&v0);
                float2 v1 = *(const float2*)&hc[hbase + (ktL + j + 1) * 8 + tq * 2];
                mma_tf32(accB4, &wreg[(j + 1) * 4], (const uint32_t*)&v1);
            }

            // ---- wait for peer h of this step (usually already arrived) ----
            if (s > 0) {
                mbar_wait_parity((s & 1) ? mbar1 : mbar0, ((s - 1) >> 1) & 1);
            }

            // ---- phase R: peer-half k ----
#pragma unroll
            for (int j = 0; j < 10; j += 2) {
                float2 v0 = *(const float2*)&hc[hbase + (ktR + j) * 8 + tq * 2];
                mma_tf32(accA, &wreg[40 + j * 4], (const uint32_t*)&v0);
                float2 v1 = *(const float2*)&hc[hbase + (ktR + j + 1) * 8 + tq * 2];
                mma_tf32(accB4, &wreg[40 + (j + 1) * 4], (const uint32_t*)&v1);
            }

            const int lr = wid * 16;
            *(float2*)&gh[(lr + grp) * 8 + 2 * tq] =
                make_float2(accA[0] + accB4[0], accA[1] + accB4[1]);
            *(float2*)&gh[(lr + 8 + grp) * 8 + 2 * tq] =
                make_float2(accA[2] + accB4[2], accA[3] + accB4[3]);
        }
        cp_wait1();        // gi for step s fully staged (group s+1 may be pending)
        __syncthreads();

        const int t = dir ? (Tt - 1 - s) : s;
        const int nxt = cur ^ 1;
        {
            float gir = gis[cur][tid], giz = gis[cur][512 + tid], gin = gis[cur][1024 + tid];
            float r = fmaf(tanh_ap(0.5f * (gir + gh[uA * 8 + bA] + bhrA)), 0.5f, 0.5f);
            float z = fmaf(tanh_ap(0.5f * (giz + gh[(80 + uA) * 8 + bA] + bhzA)), 0.5f, 0.5f);
            float n = tanh_ap(gin + r * (gh[(160 + uA) * 8 + bA] + bhnA));
            hA = fmaf(z, hA - n, n);
            uint32_t htf = f2tf32(hA);
            *(uint32_t*)&hbuf[nxt][bA * HST + pgA] = htf;
            st_cluster_u32(prA[nxt], htf);
            if (layer == 0)
                yout[((size_t)t * 320 + dir * Hh + gA) * 256 + b0 + bA] = hA;
        }
        if (hasB) {
            float gir = gis[cur][1536 + tid], giz = gis[cur][1664 + tid], gin = gis[cur][1792 + tid];
            float r = fmaf(tanh_ap(0.5f * (gir + gh[uB * 8 + bA] + bhrB)), 0.5f, 0.5f);
            float z = fmaf(tanh_ap(0.5f * (giz + gh[(80 + uB) * 8 + bA] + bhzB)), 0.5f, 0.5f);
            float n = tanh_ap(gin + r * (gh[(160 + uB) * 8 + bA] + bhnB));
            hB = fmaf(z, hB - n, n);
            uint32_t htf = f2tf32(hB);
            *(uint32_t*)&hbuf[nxt][bA * HST + pgB] = htf;
            st_cluster_u32(prB[nxt], htf);
            if (layer == 0)
                yout[((size_t)t * 320 + dir * Hh + gB) * 256 + b0 + bA] = hB;
        }
        __syncthreads();   // combine stores visible before next phase L / release
        if (tid == 0) {
            mbar_arrive_peer((nxt & 1) ? pbar1 : pbar0);
        }
        cur = nxt;
    }

    if (layer == 1) {
        yout[((size_t)(dir * Bb) + b0 + bA) * Hh + gA] = hA;
        if (hasB) yout[((size_t)(dir * Bb) + b0 + bA) * Hh + gB] = hB;
    }
    CLUSTER_SYNC();   // no CTA exits while peer stores into its smem may be in flight
}

// ---------------------------------------------------------------------------
// K5: head
// ---------------------------------------------------------------------------
__global__ __launch_bounds__(128)
void head_kernel(const float* __restrict__ hfin,
                 const float* __restrict__ fc1w, const float* __restrict__ fc1b,
                 const float* __restrict__ fc2w, const float* __restrict__ fc2b,
                 float* __restrict__ out) {
    const int b = blockIdx.x;
    const int j = threadIdx.x;
    __shared__ float hv[320];
    __shared__ float red[4];

    for (int k = j; k < Hh; k += 128) {
        hv[k]      = hfin[(size_t)b * Hh + k];
        hv[Hh + k] = hfin[(size_t)Bb * Hh + (size_t)b * Hh + k];
    }
    __syncthreads();

    float acc = fc1b[j];
    const float* wr = fc1w + (size_t)j * 320;
#pragma unroll 8
    for (int k = 0; k < 320; k++) acc += wr[k] * hv[k];
    float v = fmaxf(acc, 0.f) * fc2w[j];

#pragma unroll
    for (int o = 16; o > 0; o >>= 1) v += __shfl_down_sync(0xffffffffu, v, o);
    if ((j & 31) == 0) red[j >> 5] = v;
    __syncthreads();
    if (j == 0) out[b] = red[0] + red[1] + red[2] + red[3] + fc2b[0];
}

// ---------------------------------------------------------------------------
// kernel_launch
// ---------------------------------------------------------------------------
extern "C" void kernel_launch(void* const* d_in, const int* in_sizes, int n_in,
                              void* d_out, int out_size) {
    const int*   x        = (const int*)  d_in[0];
    const float* emb      = (const float*)d_in[1];
    const float* Wih_l0f  = (const float*)d_in[2];
    const float* Whh_l0f  = (const float*)d_in[3];
    const float* bih_l0f  = (const float*)d_in[4];
    const float* bhh_l0f  = (const float*)d_in[5];
    const float* Wih_l0b  = (const float*)d_in[6];
    const float* Whh_l0b  = (const float*)d_in[7];
    const float* bih_l0b  = (const float*)d_in[8];
    const float* bhh_l0b  = (const float*)d_in[9];
    const float* Wih_l1f  = (const float*)d_in[10];
    const float* Whh_l1f  = (const float*)d_in[11];
    const float* bih_l1f  = (const float*)d_in[12];
    const float* bhh_l1f  = (const float*)d_in[13];
    const float* Wih_l1b  = (const float*)d_in[14];
    const float* Whh_l1b  = (const float*)d_in[15];
    const float* bih_l1b  = (const float*)d_in[16];
    const float* bhh_l1b  = (const float*)d_in[17];
    const float* fc1_w    = (const float*)d_in[18];
    const float* fc1_b    = (const float*)d_in[19];
    const float* fc2_w    = (const float*)d_in[20];
    const float* fc2_b    = (const float*)d_in[21];
    float* out = (float*)d_out;

    float *gi0, *gi1, *y0, *hfin;
    cudaGetSymbolAddress((void**)&gi0,  g_gi0);
    cudaGetSymbolAddress((void**)&gi1,  g_gi1);
    cudaGetSymbolAddress((void**)&y0,   g_y0);
    cudaGetSymbolAddress((void**)&hfin, g_hfin);

    {
        dim3 grid(Mrows / 128, G3 / 96, 2);
        gates_mma_kernel<128, true><<<grid, 256>>>(emb, x, Wih_l0f, Wih_l0b,
                                                   bih_l0f, bih_l0b, gi0);
    }

    scan_mma_kernel<<<dim3(64, 2), 512>>>(gi0, Whh_l0f, Whh_l0b,
                                          bhh_l0f, bhh_l0b, y0, 0);

    {
        dim3 grid(Mrows / 128, G3 / 96, 2);
        gates_mma_kernel<320, false><<<grid, 256>>>(y0, nullptr, Wih_l1f, Wih_l1b,
                                                    bih_l1f, bih_l1b, gi1);
    }

    scan_mma_kernel<<<dim3(64, 2), 512>>>(gi1, Whh_l1f, Whh_l1b,
                                          bhh_l1f, bhh_l1b, hfin, 1);

    head_kernel<<<Bb, 128>>>(hfin, fc1_w, fc1_b, fc2_w, fc2_b, out);
}